// round 12
// baseline (speedup 1.0000x reference)
#include <cuda_runtime.h>
#include <cuda_fp16.h>
#include <cstdint>

#define BATCH    16
#define N_COARSE 1024
#define N_FINE   4096
#define C_IN     256
#define C_SKIP   128
#define C_HID    256
#define NC_TOT   (BATCH * N_COARSE)   // 16384
#define NF_TOT   (BATCH * N_FINE)     // 65536

// ---------------- scratch (static device globals; no runtime alloc) --------
__device__ __half  g_yh[NC_TOT * C_HID];                // 8 MB fp16
__device__ int     g_idx[NF_TOT * 3];
__device__ float   g_w[NF_TOT * 3];
__device__ __half  g_xh[NC_TOT * C_IN];                 // [16384, 256] fp16
__device__ __half  g_xsh[NF_TOT * C_SKIP];              // [65536, 128] fp16
__device__ __half  g_h1h[(size_t)NF_TOT * C_HID];       // [65536, 256] fp16
__device__ __half  g_w1a[C_HID * C_IN];                 // [256 n, 256 k] (W1a^T)
__device__ __half  g_w1b[C_HID * C_SKIP];               // [256 n, 128 k] (W1b^T)
__device__ __half  g_w2t[C_HID * C_HID];                // [256 n, 256 k] (W2^T)
// flags: [0]=knn CTA counter, [1..16]=per-cloud G1 tile counter, [32..543]=per-rowblock G2 counter
__device__ int     g_flags[544];

// ---------------- PTX helpers (portable, no arch-gated features) -----------
__device__ __forceinline__ uint32_t smem_u32(const void* p) {
    return (uint32_t)__cvta_generic_to_shared(p);
}
__device__ __forceinline__ void cp16(uint32_t dst, const void* src) {
    asm volatile("cp.async.cg.shared.global [%0], [%1], 16;" :: "r"(dst), "l"(src));
}
#define CP_COMMIT()  asm volatile("cp.async.commit_group;" ::: "memory")
#define CP_WAIT(n)   asm volatile("cp.async.wait_group %0;" :: "n"(n) : "memory")
#define LDSM4(r, addr) \
    asm volatile("ldmatrix.sync.aligned.m8n8.x4.shared.b16 {%0,%1,%2,%3}, [%4];" \
        : "=r"((r)[0]), "=r"((r)[1]), "=r"((r)[2]), "=r"((r)[3]) : "r"(addr))

__device__ __forceinline__ void mma16816(float* c, const uint32_t* a, const uint32_t* b) {
    asm volatile(
        "mma.sync.aligned.m16n8k16.row.col.f32.f16.f16.f32 "
        "{%0,%1,%2,%3}, {%4,%5,%6,%7}, {%8,%9}, {%0,%1,%2,%3};"
        : "+f"(c[0]), "+f"(c[1]), "+f"(c[2]), "+f"(c[3])
        : "r"(a[0]), "r"(a[1]), "r"(a[2]), "r"(a[3]), "r"(b[0]), "r"(b[1]));
}

// ---------------- prep: xh cast (blocks 0..4095) + weight transpose (160) ---
#define XH_BLOCKS (NC_TOT * C_IN / 4 / 256)   // 4096

__global__ __launch_bounds__(256) void prep_main(
    const float* __restrict__ x, __half* __restrict__ xh,
    const float* __restrict__ W1, const float* __restrict__ W2,
    __half* __restrict__ w1a, __half* __restrict__ w1b, __half* __restrict__ w2t)
{
    __shared__ float tile[32][33];
    const int blk = blockIdx.x;
    const int tid = threadIdx.x;
    if (blk < XH_BLOCKS) {
        int i = blk * 256 + tid;
        float4 v = *(const float4*)(x + (size_t)i * 4);
        __half2 a = __halves2half2(__float2half_rn(v.x), __float2half_rn(v.y));
        __half2 b = __halves2half2(__float2half_rn(v.z), __float2half_rn(v.w));
        *(uint2*)(xh + (size_t)i * 4) = make_uint2(*(uint32_t*)&a, *(uint32_t*)&b);
        return;
    }
    const int tb = blk - XH_BLOCKS;       // 0..159 (96 for W1, 64 for W2)
    const float* W; int k0, n0; bool isW1;
    if (tb < 96) { W = W1; k0 = (tb >> 3) * 32; n0 = (tb & 7) * 32; isW1 = true; }
    else { int u = tb - 96; W = W2; k0 = (u >> 3) * 32; n0 = (u & 7) * 32; isW1 = false; }

    const int tr = tid >> 5, tc = tid & 31;
    #pragma unroll
    for (int i = 0; i < 4; i++)
        tile[tr + 8 * i][tc] = W[(size_t)(k0 + tr + 8 * i) * C_HID + n0 + tc];
    __syncthreads();

    const int ln = tid >> 3;              // 0..31
    const int kq = (tid & 7) * 4;         // 0,4,..28
    const int n = n0 + ln;
    __half h[4];
    #pragma unroll
    for (int j = 0; j < 4; j++)
        h[j] = __float2half_rn(tile[kq + j][ln]);
    __half* o; int K, k;
    if (isW1) {
        if (k0 < C_IN) { K = C_IN;  k = k0 + kq;          o = w1a + (size_t)n * K; }
        else           { K = C_SKIP; k = k0 - C_IN + kq;  o = w1b + (size_t)n * K; }
    } else             { K = C_HID; k = k0 + kq;          o = w2t + (size_t)n * K; }
    *(uint2*)&o[k] = *(uint2*)h;
}

// xsh cast (side stream)
__global__ void cast_act(const float* __restrict__ in, __half* __restrict__ out, int n4)
{
    int i = blockIdx.x * blockDim.x + threadIdx.x;
    if (i >= n4) return;
    float4 v = *(const float4*)(in + (size_t)i * 4);
    __half2 a = __halves2half2(__float2half_rn(v.x), __float2half_rn(v.y));
    __half2 b = __halves2half2(__float2half_rn(v.z), __float2half_rn(v.w));
    *(uint2*)(out + (size_t)i * 4) = make_uint2(*(uint32_t*)&a, *(uint32_t*)&b);
}

// ---------------- GEMM tile body (device fn, compile-time shapes) ----------
#define PITCH 40                        // fp16 per smem row (80B)
#define OP_BYTES (128 * PITCH * 2)      // 10240 per operand per stage
#define STAGE_BYTES (2 * OP_BYTES)      // 20480
#define NSTAGE 4
#define SM_BYTES (NSTAGE * STAGE_BYTES) // 81920

// mode: 0 = raw -> fp16 outh, 1 = bias+gather(Y fp16)+relu -> fp16 outh,
//       2 = bias+relu -> fp32 outf
// wflags: if non-null, tid0 spins AFTER the mainloop (deps consumed only in epilogue)
template <int NCHUNKS, int LDA, int LDB>
__device__ __forceinline__ void gemm_tile(
    int mode,
    const __half* __restrict__ A, const __half* __restrict__ Bw,
    const float* __restrict__ bias, float* __restrict__ outf,
    __half* __restrict__ outh,
    const __half* __restrict__ Y, const int* __restrict__ gidx,
    const float* __restrict__ gw,
    const int* wflags, int wi0, int wc0, int wi1, int wc1,
    int row0, int col0, char* smem)
{
    const uint32_t sb = smem_u32(smem);
    const int tid = threadIdx.x;
    const int wid = tid >> 5, lane = tid & 31;
    const int g = lane >> 2, t = lane & 3;
    const int wm = wid & 3, wn = wid >> 2;        // 4 x 2 warp grid

    const int lrow = tid >> 1;                    // 0..127
    const int lch  = (tid & 1) * 2;               // 16B-chunk 0 or 2
    const uint32_t dA0 = sb + (uint32_t)(lrow * 80 + lch * 16);
    const uint32_t dB0 = dA0 + OP_BYTES;
    const __half* gA = A + (size_t)(row0 + lrow) * LDA + lch * 8;
    const __half* gB = Bw + (size_t)(col0 + lrow) * LDB + lch * 8;

    uint32_t aAddr[2], bAddr[4];
    #pragma unroll
    for (int mt = 0; mt < 2; mt++)
        aAddr[mt] = sb + (uint32_t)(((wm * 32 + mt * 16 + (lane & 15)) * PITCH
                                     + (lane >> 4) * 8) * 2);
    #pragma unroll
    for (int p = 0; p < 4; p++)
        bAddr[p] = sb + OP_BYTES + (uint32_t)(((wn * 64 + p * 16 + (lane & 7)
                                     + ((lane >> 4) & 1) * 8) * PITCH
                                     + ((lane >> 3) & 1) * 8) * 2);

    float acc[2][8][4];
    #pragma unroll
    for (int mt = 0; mt < 2; mt++)
        #pragma unroll
        for (int nt = 0; nt < 8; nt++)
            #pragma unroll
            for (int e = 0; e < 4; e++) acc[mt][nt][e] = 0.f;

    #pragma unroll
    for (int s = 0; s < NSTAGE - 1; s++) {
        const uint32_t dA = dA0 + s * STAGE_BYTES;
        const uint32_t dB = dB0 + s * STAGE_BYTES;
        cp16(dA, gA + s * 32); cp16(dA + 16, gA + s * 32 + 8);
        cp16(dB, gB + s * 32); cp16(dB + 16, gB + s * 32 + 8);
        CP_COMMIT();
    }

    #pragma unroll
    for (int c = 0; c < NCHUNKS; c++) {
        if (c + (NSTAGE - 1) <= NCHUNKS) { CP_WAIT(NSTAGE - 2); }
        else if (c + 2 == NCHUNKS)       { CP_WAIT(1); }
        else                             { CP_WAIT(0); }
        __syncthreads();

        if (c + NSTAGE - 1 < NCHUNKS) {
            const int c2 = c + NSTAGE - 1;
            const uint32_t dA = dA0 + (c2 % NSTAGE) * STAGE_BYTES;
            const uint32_t dB = dB0 + (c2 % NSTAGE) * STAGE_BYTES;
            cp16(dA, gA + c2 * 32); cp16(dA + 16, gA + c2 * 32 + 8);
            cp16(dB, gB + c2 * 32); cp16(dB + 16, gB + c2 * 32 + 8);
            CP_COMMIT();
        }

        const uint32_t so = (c % NSTAGE) * STAGE_BYTES;
        #pragma unroll
        for (int ks = 0; ks < 2; ks++) {
            const uint32_t ko = so + ks * 32;
            uint32_t a[2][4], bq[4][4];
            LDSM4(a[0], aAddr[0] + ko);
            LDSM4(a[1], aAddr[1] + ko);
            LDSM4(bq[0], bAddr[0] + ko);
            LDSM4(bq[1], bAddr[1] + ko);
            LDSM4(bq[2], bAddr[2] + ko);
            LDSM4(bq[3], bAddr[3] + ko);
            #pragma unroll
            for (int mt = 0; mt < 2; mt++)
                #pragma unroll
                for (int nt = 0; nt < 8; nt++)
                    mma16816(acc[mt][nt], a[mt], &bq[nt >> 1][(nt & 1) * 2]);
        }
    }

    // deferred dependency wait (epilogue inputs only)
    if (wflags) {
        if (tid == 0) {
            volatile int* vf = (volatile int*)wflags;
            while (vf[wi0] < wc0) __nanosleep(100);
            if (wi1 >= 0) while (vf[wi1] < wc1) __nanosleep(100);
        }
        __syncthreads();
        __threadfence();
    }

    // epilogue
    #pragma unroll
    for (int mt = 0; mt < 2; mt++) {
        #pragma unroll
        for (int half = 0; half < 2; half++) {
            const int r = row0 + wm * 32 + mt * 16 + g + half * 8;
            int i0 = 0, i1 = 0, i2 = 0;
            float w0 = 0.f, w1 = 0.f, w2 = 0.f;
            if (mode == 1) {
                i0 = gidx[r * 3 + 0]; i1 = gidx[r * 3 + 1]; i2 = gidx[r * 3 + 2];
                w0 = gw[r * 3 + 0]; w1 = gw[r * 3 + 1]; w2 = gw[r * 3 + 2];
            }
            #pragma unroll
            for (int nt = 0; nt < 8; nt++) {
                const int ccol = col0 + wn * 64 + nt * 8 + 2 * t;
                float vx = acc[mt][nt][half * 2 + 0];
                float vy = acc[mt][nt][half * 2 + 1];
                if (mode == 0) {
                    __half2 h2 = __halves2half2(__float2half_rn(vx), __float2half_rn(vy));
                    *(__half2*)&outh[(size_t)r * C_HID + ccol] = h2;
                } else if (mode == 2) {
                    float2 bb = *(const float2*)&bias[ccol];
                    vx = fmaxf(vx + bb.x, 0.f);
                    vy = fmaxf(vy + bb.y, 0.f);
                    *(float2*)&outf[(size_t)r * C_HID + ccol] = make_float2(vx, vy);
                } else {
                    float2 bb = *(const float2*)&bias[ccol];
                    float2 y0 = __half22float2(*(const __half2*)&Y[(size_t)i0 * C_HID + ccol]);
                    float2 y1 = __half22float2(*(const __half2*)&Y[(size_t)i1 * C_HID + ccol]);
                    float2 y2 = __half22float2(*(const __half2*)&Y[(size_t)i2 * C_HID + ccol]);
                    vx = fmaxf(vx + bb.x + w0 * y0.x + w1 * y1.x + w2 * y2.x, 0.f);
                    vy = fmaxf(vy + bb.y + w0 * y0.y + w1 * y1.y + w2 * y2.y, 0.f);
                    __half2 h2 = __halves2half2(__float2half_rn(vx), __float2half_rn(vy));
                    *(__half2*)&outh[(size_t)r * C_HID + ccol] = h2;
                }
            }
        }
    }
}

// ---------------- mega kernel: KNN -> G1 -> G2 -> G3, flag dependencies -----
#define KNN_BLOCKS 256     // 256 blocks x 256 threads, 1 fine point/thread
#define G1_TILES 256
#define G2_TILES 1024
#define G3_TILES 1024

__global__ __launch_bounds__(256, 2) void mega_gemm(
    const float* __restrict__ pos, const float* __restrict__ pos_skip,
    const __half* __restrict__ xh, const __half* __restrict__ xsh,
    const __half* __restrict__ h1_c,
    const __half* __restrict__ w1a, const __half* __restrict__ w1b,
    const __half* __restrict__ w2t,
    const float* __restrict__ b1, const float* __restrict__ b2,
    __half* __restrict__ yh, __half* __restrict__ h1,
    float* __restrict__ outp,
    int* __restrict__ gidx, float* __restrict__ gw,
    int* __restrict__ flags)
{
    extern __shared__ __align__(16) char smem[];
    const int t = blockIdx.x;
    const int tid = threadIdx.x;
    volatile int* vf = (volatile int*)flags;

    if (t < KNN_BLOCKS) {
        // ---- kNN phase: cloud b = t/16, 256 fine points per block ----
        float4* sp = (float4*)smem;       // 16 KB (within 80KB dynamic alloc)
        const int b = t >> 4;
        const int chunk = t & 15;
        const float* pc = pos + (size_t)b * N_COARSE * 3;
        for (int i = tid; i < N_COARSE; i += 256)
            sp[i] = make_float4(pc[i * 3 + 0], pc[i * 3 + 1], pc[i * 3 + 2], 0.f);
        __syncthreads();

        const int f = b * N_FINE + chunk * 256 + tid;
        const float px = pos_skip[f * 3 + 0];
        const float py = pos_skip[f * 3 + 1];
        const float pz = pos_skip[f * 3 + 2];

        float d0 = 3.4e38f, d1 = 3.4e38f, d2 = 3.4e38f;
        int i0 = 0, i1 = 0, i2 = 0;
        #pragma unroll 4
        for (int j = 0; j < N_COARSE; j++) {
            float4 p = sp[j];
            float dx = px - p.x, dy = py - p.y, dz = pz - p.z;
            float d = dx * dx + dy * dy + dz * dz;
            if (d < d2) {
                if (d < d1) {
                    d2 = d1; i2 = i1;
                    if (d < d0) { d1 = d0; i1 = i0; d0 = d; i0 = j; }
                    else        { d1 = d;  i1 = j; }
                } else { d2 = d; i2 = j; }
            }
        }
        float w0 = 1.0f / fmaxf(d0, 1e-16f);
        float w1 = 1.0f / fmaxf(d1, 1e-16f);
        float w2 = 1.0f / fmaxf(d2, 1e-16f);
        float inv = 1.0f / (w0 + w1 + w2);
        gidx[f * 3 + 0] = b * N_COARSE + i0;
        gidx[f * 3 + 1] = b * N_COARSE + i1;
        gidx[f * 3 + 2] = b * N_COARSE + i2;
        gw[f * 3 + 0] = w0 * inv;
        gw[f * 3 + 1] = w1 * inv;
        gw[f * 3 + 2] = w2 * inv;

        __threadfence();
        __syncthreads();
        if (tid == 0) atomicAdd(&flags[0], 1);
    } else if (t < KNN_BLOCKS + G1_TILES) {
        const int u = t - KNN_BLOCKS;
        const int bx = u & 1, by = u >> 1;
        gemm_tile<8, 256, 256>(0, xh, w1a, nullptr, nullptr, yh,
                               nullptr, nullptr, nullptr,
                               nullptr, 0, 0, -1, 0,
                               by * 128, bx * 128, smem);
        __threadfence();
        __syncthreads();
        if (tid == 0) atomicAdd(&flags[1 + (by >> 3)], 1);
    } else if (t < KNN_BLOCKS + G1_TILES + G2_TILES) {
        const int u = t - KNN_BLOCKS - G1_TILES;
        const int bx = u & 1, by = u >> 1;
        const int cloud = by >> 5;
        // no pre-wait: kNN/y are consumed only in the epilogue (deferred wait)
        gemm_tile<4, 128, 128>(1, xsh, w1b, b1, nullptr, h1,
                               yh, gidx, gw,
                               flags, 0, KNN_BLOCKS, 1 + cloud, 16,
                               by * 128, bx * 128, smem);
        __threadfence();
        __syncthreads();
        if (tid == 0) atomicAdd(&flags[32 + by], 1);
    } else {
        const int u = t - KNN_BLOCKS - G1_TILES - G2_TILES;
        const int bx = u & 1, by = u >> 1;
        if (tid == 0) {
            while (vf[32 + by] < 2) __nanosleep(200);
        }
        __syncthreads();
        __threadfence();
        gemm_tile<8, 256, 256>(2, h1_c, w2t, b2, outp, nullptr,
                               nullptr, nullptr, nullptr,
                               nullptr, 0, 0, -1, 0,
                               by * 128, bx * 128, smem);
    }
}

// batch_skip int32 -> float (tuple tail)
__global__ void cast_batch_kernel(const int* __restrict__ b, float* __restrict__ out, int n)
{
    int i = blockIdx.x * blockDim.x + threadIdx.x;
    if (i < n) out[i] = (float)b[i];
}

// ---------------------------------------------------------------------------
extern "C" void kernel_launch(void* const* d_in, const int* in_sizes, int n_in,
                              void* d_out, int out_size)
{
    (void)in_sizes; (void)n_in;
    const float* x        = (const float*)d_in[0];
    const float* pos      = (const float*)d_in[1];
    const float* x_skip   = (const float*)d_in[2];
    const float* pos_skip = (const float*)d_in[3];
    const float* W1       = (const float*)d_in[4];
    const float* b1       = (const float*)d_in[5];
    const float* W2       = (const float*)d_in[6];
    const float* b2       = (const float*)d_in[7];

    float* w; int *idx, *flags;
    __half *yh, *xh, *xsh, *h1h, *w1a, *w1b, *w2t;
    cudaGetSymbolAddress((void**)&yh,    g_yh);
    cudaGetSymbolAddress((void**)&idx,   g_idx);
    cudaGetSymbolAddress((void**)&w,     g_w);
    cudaGetSymbolAddress((void**)&xh,    g_xh);
    cudaGetSymbolAddress((void**)&xsh,   g_xsh);
    cudaGetSymbolAddress((void**)&h1h,   g_h1h);
    cudaGetSymbolAddress((void**)&w1a,   g_w1a);
    cudaGetSymbolAddress((void**)&w1b,   g_w1b);
    cudaGetSymbolAddress((void**)&w2t,   g_w2t);
    cudaGetSymbolAddress((void**)&flags, g_flags);

    static bool init_done = false;
    static cudaStream_t s_aux;
    static cudaEvent_t ev_fork, ev_aux;
    if (!init_done) {
        cudaFuncSetAttribute(mega_gemm, cudaFuncAttributeMaxDynamicSharedMemorySize, SM_BYTES);
        cudaStreamCreateWithFlags(&s_aux, cudaStreamNonBlocking);
        cudaEventCreateWithFlags(&ev_fork, cudaEventDisableTiming);
        cudaEventCreateWithFlags(&ev_aux, cudaEventDisableTiming);
        init_done = true;
    }

    // reset flags (mega's knn phase increments flags[0])
    cudaMemsetAsync(flags, 0, 544 * sizeof(int), 0);
    cudaEventRecord(ev_fork, 0);

    // side stream: xsh cast (needed by G2 mainloops; mega waits on it)
    cudaStreamWaitEvent(s_aux, ev_fork, 0);
    cast_act<<<(NF_TOT * C_SKIP / 4 + 255) / 256, 256, 0, s_aux>>>(
        x_skip, xsh, NF_TOT * C_SKIP / 4);
    cudaEventRecord(ev_aux, s_aux);

    // main stream: xh cast + weight transpose in one launch
    prep_main<<<XH_BLOCKS + 160, 256>>>(x, xh, W1, W2, w1a, w1b, w2t);

    cudaStreamWaitEvent(0, ev_aux, 0);
    mega_gemm<<<KNN_BLOCKS + G1_TILES + G2_TILES + G3_TILES, 256, SM_BYTES>>>(
        pos, pos_skip, xh, xsh, h1h, w1a, w1b, w2t, b1, b2,
        yh, h1h, (float*)d_out, idx, w, flags);

    // Tuple tail: (h, pos_skip, batch_skip) — append if the harness expects it
    const long long H_ELEMS   = (long long)NF_TOT * C_HID;
    const long long POS_ELEMS = (long long)NF_TOT * 3;
    if ((long long)out_size >= H_ELEMS + POS_ELEMS) {
        cudaMemcpyAsync((float*)d_out + H_ELEMS, pos_skip,
                        POS_ELEMS * sizeof(float), cudaMemcpyDeviceToDevice);
    }
    if ((long long)out_size >= H_ELEMS + POS_ELEMS + NF_TOT) {
        const int* batch_skip = (const int*)d_in[9];
        cast_batch_kernel<<<(NF_TOT + 255) / 256, 256>>>(
            batch_skip, (float*)d_out + H_ELEMS + POS_ELEMS, NF_TOT);
    }
}

// round 13
// speedup vs baseline: 1.0696x; 1.0696x over previous
#include <cuda_runtime.h>
#include <cuda_fp16.h>
#include <cstdint>

#define BATCH    16
#define N_COARSE 1024
#define N_FINE   4096
#define C_IN     256
#define C_SKIP   128
#define C_HID    256
#define NC_TOT   (BATCH * N_COARSE)   // 16384
#define NF_TOT   (BATCH * N_FINE)     // 65536

// ---------------- scratch (static device globals; no runtime alloc) --------
__device__ __half  g_yh[NC_TOT * C_HID];                // 8 MB fp16
__device__ int     g_idx[NF_TOT * 3];
__device__ float   g_w[NF_TOT * 3];
__device__ __half  g_xh[NC_TOT * C_IN];                 // [16384, 256] fp16
__device__ __half  g_xsh[NF_TOT * C_SKIP];              // [65536, 128] fp16
__device__ __half  g_h1h[(size_t)NF_TOT * C_HID];       // [65536, 256] fp16
__device__ __half  g_w1a[C_HID * C_IN];                 // [256 n, 256 k] (W1a^T)
__device__ __half  g_w1b[C_HID * C_SKIP];               // [256 n, 128 k] (W1b^T)
__device__ __half  g_w2t[C_HID * C_HID];                // [256 n, 256 k] (W2^T)
// flags: [0]=knn CTA counter, [1..16]=per-cloud G1 tile counter, [32..543]=per-rowblock G2 counter
__device__ int     g_flags[544];

// ---------------- PTX helpers (portable, no arch-gated features) -----------
__device__ __forceinline__ uint32_t smem_u32(const void* p) {
    return (uint32_t)__cvta_generic_to_shared(p);
}
__device__ __forceinline__ void cp16(uint32_t dst, const void* src) {
    asm volatile("cp.async.cg.shared.global [%0], [%1], 16;" :: "r"(dst), "l"(src));
}
#define CP_COMMIT()  asm volatile("cp.async.commit_group;" ::: "memory")
#define CP_WAIT(n)   asm volatile("cp.async.wait_group %0;" :: "n"(n) : "memory")
#define LDSM4(r, addr) \
    asm volatile("ldmatrix.sync.aligned.m8n8.x4.shared.b16 {%0,%1,%2,%3}, [%4];" \
        : "=r"((r)[0]), "=r"((r)[1]), "=r"((r)[2]), "=r"((r)[3]) : "r"(addr))

__device__ __forceinline__ void mma16816(float* c, const uint32_t* a, const uint32_t* b) {
    asm volatile(
        "mma.sync.aligned.m16n8k16.row.col.f32.f16.f16.f32 "
        "{%0,%1,%2,%3}, {%4,%5,%6,%7}, {%8,%9}, {%0,%1,%2,%3};"
        : "+f"(c[0]), "+f"(c[1]), "+f"(c[2]), "+f"(c[3])
        : "r"(a[0]), "r"(a[1]), "r"(a[2]), "r"(a[3]), "r"(b[0]), "r"(b[1]));
}

// ---------------- kNN (k=3): 1 point/thread, float4 smem, self-signaling ----
__global__ __launch_bounds__(128) void knn_kernel(
    const float* __restrict__ pos, const float* __restrict__ pos_skip,
    int* __restrict__ gidx, float* __restrict__ gw, int* __restrict__ flags)
{
    __shared__ float4 sp[N_COARSE];   // 16 KB
    const int chunks = N_FINE / 128;              // 32
    const int b = blockIdx.x / chunks;
    const int chunk = blockIdx.x % chunks;
    const int tid = threadIdx.x;

    const float* pc = pos + (size_t)b * N_COARSE * 3;
    for (int i = tid; i < N_COARSE; i += 128)
        sp[i] = make_float4(pc[i * 3 + 0], pc[i * 3 + 1], pc[i * 3 + 2], 0.f);
    __syncthreads();

    const int f = b * N_FINE + chunk * 128 + tid;
    const float px = pos_skip[f * 3 + 0];
    const float py = pos_skip[f * 3 + 1];
    const float pz = pos_skip[f * 3 + 2];

    float d0 = 3.4e38f, d1 = 3.4e38f, d2 = 3.4e38f;
    int i0 = 0, i1 = 0, i2 = 0;
    #pragma unroll 4
    for (int j = 0; j < N_COARSE; j++) {
        float4 p = sp[j];
        float dx = px - p.x, dy = py - p.y, dz = pz - p.z;
        float d = dx * dx + dy * dy + dz * dz;
        if (d < d2) {
            if (d < d1) {
                d2 = d1; i2 = i1;
                if (d < d0) { d1 = d0; i1 = i0; d0 = d; i0 = j; }
                else        { d1 = d;  i1 = j; }
            } else { d2 = d; i2 = j; }
        }
    }
    float w0 = 1.0f / fmaxf(d0, 1e-16f);
    float w1 = 1.0f / fmaxf(d1, 1e-16f);
    float w2 = 1.0f / fmaxf(d2, 1e-16f);
    float inv = 1.0f / (w0 + w1 + w2);
    gidx[f * 3 + 0] = b * N_COARSE + i0;
    gidx[f * 3 + 1] = b * N_COARSE + i1;
    gidx[f * 3 + 2] = b * N_COARSE + i2;
    gw[f * 3 + 0] = w0 * inv;
    gw[f * 3 + 1] = w1 * inv;
    gw[f * 3 + 2] = w2 * inv;

    __threadfence();
    __syncthreads();
    if (tid == 0) atomicAdd(&flags[0], 1);
}

// ---------------- casts ------------------------------------------------------
__global__ void cast_act(const float* __restrict__ in, __half* __restrict__ out, int n4)
{
    int i = blockIdx.x * blockDim.x + threadIdx.x;
    if (i >= n4) return;
    float4 v = *(const float4*)(in + (size_t)i * 4);
    __half2 a = __halves2half2(__float2half_rn(v.x), __float2half_rn(v.y));
    __half2 b = __halves2half2(__float2half_rn(v.z), __float2half_rn(v.w));
    *(uint2*)(out + (size_t)i * 4) = make_uint2(*(uint32_t*)&a, *(uint32_t*)&b);
}

// tiled weight transpose-cast: W1 [384,256] -> w1a/w1b, W2 [256,256] -> w2t
__global__ __launch_bounds__(256) void cast_w_tiled(
    const float* __restrict__ W1, const float* __restrict__ W2,
    __half* __restrict__ w1a, __half* __restrict__ w1b, __half* __restrict__ w2t)
{
    __shared__ float tile[32][33];
    const int tb = blockIdx.x;            // 0..159 (96 for W1, 64 for W2)
    const int tid = threadIdx.x;
    const float* W; int k0, n0; bool isW1;
    if (tb < 96) { W = W1; k0 = (tb >> 3) * 32; n0 = (tb & 7) * 32; isW1 = true; }
    else { int u = tb - 96; W = W2; k0 = (u >> 3) * 32; n0 = (u & 7) * 32; isW1 = false; }

    const int tr = tid >> 5, tc = tid & 31;
    #pragma unroll
    for (int i = 0; i < 4; i++)
        tile[tr + 8 * i][tc] = W[(size_t)(k0 + tr + 8 * i) * C_HID + n0 + tc];
    __syncthreads();

    const int ln = tid >> 3;              // 0..31
    const int kq = (tid & 7) * 4;         // 0,4,..28
    const int n = n0 + ln;
    __half h[4];
    #pragma unroll
    for (int j = 0; j < 4; j++)
        h[j] = __float2half_rn(tile[kq + j][ln]);
    __half* o; int K, k;
    if (isW1) {
        if (k0 < C_IN) { K = C_IN;  k = k0 + kq;          o = w1a + (size_t)n * K; }
        else           { K = C_SKIP; k = k0 - C_IN + kq;  o = w1b + (size_t)n * K; }
    } else             { K = C_HID; k = k0 + kq;          o = w2t + (size_t)n * K; }
    *(uint2*)&o[k] = *(uint2*)h;
}

// ---------------- GEMM tile body (device fn, compile-time shapes) ----------
#define PITCH 40                        // fp16 per smem row (80B)
#define OP_BYTES (128 * PITCH * 2)      // 10240 per operand per stage
#define STAGE_BYTES (2 * OP_BYTES)      // 20480
#define NSTAGE 4
#define SM_BYTES (NSTAGE * STAGE_BYTES) // 81920

// mode: 0 = raw -> fp16 outh, 1 = bias+gather(Y fp16)+relu -> fp16 outh,
//       2 = bias+relu -> fp32 outf
// wflags: if non-null, tid0 spins AFTER the mainloop (deps consumed only in epilogue)
template <int NCHUNKS, int LDA, int LDB>
__device__ __forceinline__ void gemm_tile(
    int mode,
    const __half* __restrict__ A, const __half* __restrict__ Bw,
    const float* __restrict__ bias, float* __restrict__ outf,
    __half* __restrict__ outh,
    const __half* __restrict__ Y, const int* __restrict__ gidx,
    const float* __restrict__ gw,
    const int* wflags, int wi0, int wc0, int wi1, int wc1,
    int row0, int col0, char* smem)
{
    const uint32_t sb = smem_u32(smem);
    const int tid = threadIdx.x;
    const int wid = tid >> 5, lane = tid & 31;
    const int g = lane >> 2, t = lane & 3;
    const int wm = wid & 3, wn = wid >> 2;        // 4 x 2 warp grid

    const int lrow = tid >> 1;                    // 0..127
    const int lch  = (tid & 1) * 2;               // 16B-chunk 0 or 2
    const uint32_t dA0 = sb + (uint32_t)(lrow * 80 + lch * 16);
    const uint32_t dB0 = dA0 + OP_BYTES;
    const __half* gA = A + (size_t)(row0 + lrow) * LDA + lch * 8;
    const __half* gB = Bw + (size_t)(col0 + lrow) * LDB + lch * 8;

    uint32_t aAddr[2], bAddr[4];
    #pragma unroll
    for (int mt = 0; mt < 2; mt++)
        aAddr[mt] = sb + (uint32_t)(((wm * 32 + mt * 16 + (lane & 15)) * PITCH
                                     + (lane >> 4) * 8) * 2);
    #pragma unroll
    for (int p = 0; p < 4; p++)
        bAddr[p] = sb + OP_BYTES + (uint32_t)(((wn * 64 + p * 16 + (lane & 7)
                                     + ((lane >> 4) & 1) * 8) * PITCH
                                     + ((lane >> 3) & 1) * 8) * 2);

    float acc[2][8][4];
    #pragma unroll
    for (int mt = 0; mt < 2; mt++)
        #pragma unroll
        for (int nt = 0; nt < 8; nt++)
            #pragma unroll
            for (int e = 0; e < 4; e++) acc[mt][nt][e] = 0.f;

    #pragma unroll
    for (int s = 0; s < NSTAGE - 1; s++) {
        const uint32_t dA = dA0 + s * STAGE_BYTES;
        const uint32_t dB = dB0 + s * STAGE_BYTES;
        cp16(dA, gA + s * 32); cp16(dA + 16, gA + s * 32 + 8);
        cp16(dB, gB + s * 32); cp16(dB + 16, gB + s * 32 + 8);
        CP_COMMIT();
    }

    #pragma unroll
    for (int c = 0; c < NCHUNKS; c++) {
        if (c + (NSTAGE - 1) <= NCHUNKS) { CP_WAIT(NSTAGE - 2); }
        else if (c + 2 == NCHUNKS)       { CP_WAIT(1); }
        else                             { CP_WAIT(0); }
        __syncthreads();

        if (c + NSTAGE - 1 < NCHUNKS) {
            const int c2 = c + NSTAGE - 1;
            const uint32_t dA = dA0 + (c2 % NSTAGE) * STAGE_BYTES;
            const uint32_t dB = dB0 + (c2 % NSTAGE) * STAGE_BYTES;
            cp16(dA, gA + c2 * 32); cp16(dA + 16, gA + c2 * 32 + 8);
            cp16(dB, gB + c2 * 32); cp16(dB + 16, gB + c2 * 32 + 8);
            CP_COMMIT();
        }

        const uint32_t so = (c % NSTAGE) * STAGE_BYTES;
        #pragma unroll
        for (int ks = 0; ks < 2; ks++) {
            const uint32_t ko = so + ks * 32;
            uint32_t a[2][4], bq[4][4];
            LDSM4(a[0], aAddr[0] + ko);
            LDSM4(a[1], aAddr[1] + ko);
            LDSM4(bq[0], bAddr[0] + ko);
            LDSM4(bq[1], bAddr[1] + ko);
            LDSM4(bq[2], bAddr[2] + ko);
            LDSM4(bq[3], bAddr[3] + ko);
            #pragma unroll
            for (int mt = 0; mt < 2; mt++)
                #pragma unroll
                for (int nt = 0; nt < 8; nt++)
                    mma16816(acc[mt][nt], a[mt], &bq[nt >> 1][(nt & 1) * 2]);
        }
    }

    // deferred dependency wait (epilogue inputs only)
    if (wflags) {
        if (tid == 0) {
            volatile int* vf = (volatile int*)wflags;
            while (vf[wi0] < wc0) __nanosleep(100);
            if (wi1 >= 0) while (vf[wi1] < wc1) __nanosleep(100);
        }
        __syncthreads();
        __threadfence();
    }

    // epilogue
    #pragma unroll
    for (int mt = 0; mt < 2; mt++) {
        #pragma unroll
        for (int half = 0; half < 2; half++) {
            const int r = row0 + wm * 32 + mt * 16 + g + half * 8;
            int i0 = 0, i1 = 0, i2 = 0;
            float w0 = 0.f, w1 = 0.f, w2 = 0.f;
            if (mode == 1) {
                i0 = gidx[r * 3 + 0]; i1 = gidx[r * 3 + 1]; i2 = gidx[r * 3 + 2];
                w0 = gw[r * 3 + 0]; w1 = gw[r * 3 + 1]; w2 = gw[r * 3 + 2];
            }
            #pragma unroll
            for (int nt = 0; nt < 8; nt++) {
                const int ccol = col0 + wn * 64 + nt * 8 + 2 * t;
                float vx = acc[mt][nt][half * 2 + 0];
                float vy = acc[mt][nt][half * 2 + 1];
                if (mode == 0) {
                    __half2 h2 = __halves2half2(__float2half_rn(vx), __float2half_rn(vy));
                    *(__half2*)&outh[(size_t)r * C_HID + ccol] = h2;
                } else if (mode == 2) {
                    float2 bb = *(const float2*)&bias[ccol];
                    vx = fmaxf(vx + bb.x, 0.f);
                    vy = fmaxf(vy + bb.y, 0.f);
                    *(float2*)&outf[(size_t)r * C_HID + ccol] = make_float2(vx, vy);
                } else {
                    float2 bb = *(const float2*)&bias[ccol];
                    float2 y0 = __half22float2(*(const __half2*)&Y[(size_t)i0 * C_HID + ccol]);
                    float2 y1 = __half22float2(*(const __half2*)&Y[(size_t)i1 * C_HID + ccol]);
                    float2 y2 = __half22float2(*(const __half2*)&Y[(size_t)i2 * C_HID + ccol]);
                    vx = fmaxf(vx + bb.x + w0 * y0.x + w1 * y1.x + w2 * y2.x, 0.f);
                    vy = fmaxf(vy + bb.y + w0 * y0.y + w1 * y1.y + w2 * y2.y, 0.f);
                    __half2 h2 = __halves2half2(__float2half_rn(vx), __float2half_rn(vy));
                    *(__half2*)&outh[(size_t)r * C_HID + ccol] = h2;
                }
            }
        }
    }
}

// ---------------- mega kernel: G1 -> G2 -> G3 with flag dependencies --------
#define G1_TILES 256
#define G2_TILES 1024
#define G3_TILES 1024

__global__ __launch_bounds__(256, 2) void mega_gemm(
    const __half* __restrict__ xh, const __half* __restrict__ xsh,
    const __half* __restrict__ h1_c,
    const __half* __restrict__ w1a, const __half* __restrict__ w1b,
    const __half* __restrict__ w2t,
    const float* __restrict__ b1, const float* __restrict__ b2,
    __half* __restrict__ yh, __half* __restrict__ h1,
    float* __restrict__ outp,
    const int* __restrict__ gidx, const float* __restrict__ gw,
    int* __restrict__ flags)
{
    extern __shared__ __align__(16) char smem[];
    const int t = blockIdx.x;
    const int tid = threadIdx.x;
    volatile int* vf = (volatile int*)flags;

    if (t < G1_TILES) {
        const int bx = t & 1, by = t >> 1;
        gemm_tile<8, 256, 256>(0, xh, w1a, nullptr, nullptr, yh,
                               nullptr, nullptr, nullptr,
                               nullptr, 0, 0, -1, 0,
                               by * 128, bx * 128, smem);
        __threadfence();
        __syncthreads();
        if (tid == 0) atomicAdd(&flags[1 + (by >> 3)], 1);
    } else if (t < G1_TILES + G2_TILES) {
        const int u = t - G1_TILES;
        const int bx = u & 1, by = u >> 1;
        const int cloud = by >> 5;
        // no pre-wait: kNN/y are consumed only in the epilogue (deferred wait)
        gemm_tile<4, 128, 128>(1, xsh, w1b, b1, nullptr, h1,
                               yh, gidx, gw,
                               flags, 0, BATCH * (N_FINE / 128), 1 + cloud, 16,
                               by * 128, bx * 128, smem);
        __threadfence();
        __syncthreads();
        if (tid == 0) atomicAdd(&flags[32 + by], 1);
    } else {
        const int u = t - G1_TILES - G2_TILES;
        const int bx = u & 1, by = u >> 1;
        if (tid == 0) {
            while (vf[32 + by] < 2) __nanosleep(200);
        }
        __syncthreads();
        __threadfence();
        gemm_tile<8, 256, 256>(2, h1_c, w2t, b2, outp, nullptr,
                               nullptr, nullptr, nullptr,
                               nullptr, 0, 0, -1, 0,
                               by * 128, bx * 128, smem);
    }
}

// batch_skip int32 -> float (tuple tail)
__global__ void cast_batch_kernel(const int* __restrict__ b, float* __restrict__ out, int n)
{
    int i = blockIdx.x * blockDim.x + threadIdx.x;
    if (i < n) out[i] = (float)b[i];
}

// ---------------------------------------------------------------------------
extern "C" void kernel_launch(void* const* d_in, const int* in_sizes, int n_in,
                              void* d_out, int out_size)
{
    (void)in_sizes; (void)n_in;
    const float* x        = (const float*)d_in[0];
    const float* pos      = (const float*)d_in[1];
    const float* x_skip   = (const float*)d_in[2];
    const float* pos_skip = (const float*)d_in[3];
    const float* W1       = (const float*)d_in[4];
    const float* b1       = (const float*)d_in[5];
    const float* W2       = (const float*)d_in[6];
    const float* b2       = (const float*)d_in[7];

    float* w; int *idx, *flags;
    __half *yh, *xh, *xsh, *h1h, *w1a, *w1b, *w2t;
    cudaGetSymbolAddress((void**)&yh,    g_yh);
    cudaGetSymbolAddress((void**)&idx,   g_idx);
    cudaGetSymbolAddress((void**)&w,     g_w);
    cudaGetSymbolAddress((void**)&xh,    g_xh);
    cudaGetSymbolAddress((void**)&xsh,   g_xsh);
    cudaGetSymbolAddress((void**)&h1h,   g_h1h);
    cudaGetSymbolAddress((void**)&w1a,   g_w1a);
    cudaGetSymbolAddress((void**)&w1b,   g_w1b);
    cudaGetSymbolAddress((void**)&w2t,   g_w2t);
    cudaGetSymbolAddress((void**)&flags, g_flags);

    static bool init_done = false;
    static cudaStream_t s_knn, s_aux;
    static cudaEvent_t ev_fork, ev_knn, ev_aux;
    if (!init_done) {
        cudaFuncSetAttribute(mega_gemm, cudaFuncAttributeMaxDynamicSharedMemorySize, SM_BYTES);
        cudaStreamCreateWithFlags(&s_knn, cudaStreamNonBlocking);
        cudaStreamCreateWithFlags(&s_aux, cudaStreamNonBlocking);
        cudaEventCreateWithFlags(&ev_fork, cudaEventDisableTiming);
        cudaEventCreateWithFlags(&ev_knn, cudaEventDisableTiming);
        cudaEventCreateWithFlags(&ev_aux, cudaEventDisableTiming);
        init_done = true;
    }

    const long long H_ELEMS   = (long long)NF_TOT * C_HID;
    const long long POS_ELEMS = (long long)NF_TOT * 3;

    // reset flags BEFORE forking knn (knn increments flags[0])
    cudaMemsetAsync(flags, 0, 544 * sizeof(int), 0);
    cudaEventRecord(ev_fork, 0);

    // side stream 1: kNN (self-signals via flags[0])
    cudaStreamWaitEvent(s_knn, ev_fork, 0);
    knn_kernel<<<BATCH * (N_FINE / 128), 128, 0, s_knn>>>(pos, pos_skip, idx, w, flags);
    cudaEventRecord(ev_knn, s_knn);

    // side stream 2: weight cast + xsh cast (mega deps), then tuple-tail ops
    cudaStreamWaitEvent(s_aux, ev_fork, 0);
    cast_w_tiled<<<160, 256, 0, s_aux>>>(W1, W2, w1a, w1b, w2t);
    cast_act<<<(NF_TOT * C_SKIP / 4 + 255) / 256, 256, 0, s_aux>>>(
        x_skip, xsh, NF_TOT * C_SKIP / 4);
    cudaEventRecord(ev_aux, s_aux);
    // tuple tail (independent of mega; overlaps it)
    if ((long long)out_size >= H_ELEMS + POS_ELEMS) {
        cudaMemcpyAsync((float*)d_out + H_ELEMS, pos_skip,
                        POS_ELEMS * sizeof(float), cudaMemcpyDeviceToDevice, s_aux);
    }
    if ((long long)out_size >= H_ELEMS + POS_ELEMS + NF_TOT) {
        const int* batch_skip = (const int*)d_in[9];
        cast_batch_kernel<<<(NF_TOT + 255) / 256, 256, 0, s_aux>>>(
            batch_skip, (float*)d_out + H_ELEMS + POS_ELEMS, NF_TOT);
    }

    // main stream: xh cast only, then mega
    cast_act<<<(NC_TOT * C_IN / 4 + 255) / 256, 256>>>(x, xh, NC_TOT * C_IN / 4);

    cudaStreamWaitEvent(0, ev_aux, 0);
    mega_gemm<<<G1_TILES + G2_TILES + G3_TILES, 256, SM_BYTES>>>(
        xh, xsh, h1h, w1a, w1b, w2t, b1, b2,
        yh, h1h, (float*)d_out, idx, w, flags);

    // join side streams for graph completeness
    cudaStreamWaitEvent(0, ev_knn, 0);
    {
        // ensure tail ops complete before graph end
        static cudaEvent_t ev_tail = nullptr;
        if (!ev_tail) cudaEventCreateWithFlags(&ev_tail, cudaEventDisableTiming);
        cudaEventRecord(ev_tail, s_aux);
        cudaStreamWaitEvent(0, ev_tail, 0);
    }
}

// round 14
// speedup vs baseline: 1.2547x; 1.1730x over previous
#include <cuda_runtime.h>
#include <cuda_fp16.h>
#include <cstdint>

#define BATCH    16
#define N_COARSE 1024
#define N_FINE   4096
#define C_IN     256
#define C_SKIP   128
#define C_HID    256
#define NC_TOT   (BATCH * N_COARSE)   // 16384
#define NF_TOT   (BATCH * N_FINE)     // 65536

// ---------------- scratch (static device globals; no runtime alloc) --------
__device__ __half  g_yh[NC_TOT * C_HID];                // 8 MB fp16
__device__ int     g_idx[NF_TOT * 3];
__device__ float   g_w[NF_TOT * 3];
__device__ __half  g_xh[NC_TOT * C_IN];                 // [16384, 256] fp16
__device__ __half  g_xsh[NF_TOT * C_SKIP];              // [65536, 128] fp16
__device__ __half  g_w1a[C_HID * C_IN];                 // [256 n, 256 k] (W1a^T)
__device__ __half  g_w1b[C_HID * C_SKIP];               // [256 n, 128 k] (W1b^T)
__device__ __half  g_w2t[C_HID * C_HID];                // [256 n, 256 k] (W2^T)
// flags: [0]=knn CTA counter, [1..16]=per-cloud G1 tile counter
__device__ int     g_flags[64];

// ---------------- PTX helpers (portable, no arch-gated features) -----------
__device__ __forceinline__ uint32_t smem_u32(const void* p) {
    return (uint32_t)__cvta_generic_to_shared(p);
}
__device__ __forceinline__ void cp16(uint32_t dst, const void* src) {
    asm volatile("cp.async.cg.shared.global [%0], [%1], 16;" :: "r"(dst), "l"(src));
}
#define CP_COMMIT()  asm volatile("cp.async.commit_group;" ::: "memory")
#define CP_WAIT(n)   asm volatile("cp.async.wait_group %0;" :: "n"(n) : "memory")
#define LDSM4(r, addr) \
    asm volatile("ldmatrix.sync.aligned.m8n8.x4.shared.b16 {%0,%1,%2,%3}, [%4];" \
        : "=r"((r)[0]), "=r"((r)[1]), "=r"((r)[2]), "=r"((r)[3]) : "r"(addr))

__device__ __forceinline__ void mma16816(float* c, const uint32_t* a, const uint32_t* b) {
    asm volatile(
        "mma.sync.aligned.m16n8k16.row.col.f32.f16.f16.f32 "
        "{%0,%1,%2,%3}, {%4,%5,%6,%7}, {%8,%9}, {%0,%1,%2,%3};"
        : "+f"(c[0]), "+f"(c[1]), "+f"(c[2]), "+f"(c[3])
        : "r"(a[0]), "r"(a[1]), "r"(a[2]), "r"(a[3]), "r"(b[0]), "r"(b[1]));
}

// ---------------- kNN (k=3): 1 point/thread, float4 smem, self-signaling ----
__global__ __launch_bounds__(128) void knn_kernel(
    const float* __restrict__ pos, const float* __restrict__ pos_skip,
    int* __restrict__ gidx, float* __restrict__ gw, int* __restrict__ flags)
{
    __shared__ float4 sp[N_COARSE];   // 16 KB
    const int chunks = N_FINE / 128;              // 32
    const int b = blockIdx.x / chunks;
    const int chunk = blockIdx.x % chunks;
    const int tid = threadIdx.x;

    const float* pc = pos + (size_t)b * N_COARSE * 3;
    for (int i = tid; i < N_COARSE; i += 128)
        sp[i] = make_float4(pc[i * 3 + 0], pc[i * 3 + 1], pc[i * 3 + 2], 0.f);
    __syncthreads();

    const int f = b * N_FINE + chunk * 128 + tid;
    const float px = pos_skip[f * 3 + 0];
    const float py = pos_skip[f * 3 + 1];
    const float pz = pos_skip[f * 3 + 2];

    float d0 = 3.4e38f, d1 = 3.4e38f, d2 = 3.4e38f;
    int i0 = 0, i1 = 0, i2 = 0;
    #pragma unroll 4
    for (int j = 0; j < N_COARSE; j++) {
        float4 p = sp[j];
        float dx = px - p.x, dy = py - p.y, dz = pz - p.z;
        float d = dx * dx + dy * dy + dz * dz;
        if (d < d2) {
            if (d < d1) {
                d2 = d1; i2 = i1;
                if (d < d0) { d1 = d0; i1 = i0; d0 = d; i0 = j; }
                else        { d1 = d;  i1 = j; }
            } else { d2 = d; i2 = j; }
        }
    }
    float w0 = 1.0f / fmaxf(d0, 1e-16f);
    float w1 = 1.0f / fmaxf(d1, 1e-16f);
    float w2 = 1.0f / fmaxf(d2, 1e-16f);
    float inv = 1.0f / (w0 + w1 + w2);
    gidx[f * 3 + 0] = b * N_COARSE + i0;
    gidx[f * 3 + 1] = b * N_COARSE + i1;
    gidx[f * 3 + 2] = b * N_COARSE + i2;
    gw[f * 3 + 0] = w0 * inv;
    gw[f * 3 + 1] = w1 * inv;
    gw[f * 3 + 2] = w2 * inv;

    __threadfence();
    __syncthreads();
    if (tid == 0) atomicAdd(&flags[0], 1);
}

// ---------------- casts ------------------------------------------------------
__global__ void cast_act(const float* __restrict__ in, __half* __restrict__ out, int n4)
{
    int i = blockIdx.x * blockDim.x + threadIdx.x;
    if (i >= n4) return;
    float4 v = *(const float4*)(in + (size_t)i * 4);
    __half2 a = __halves2half2(__float2half_rn(v.x), __float2half_rn(v.y));
    __half2 b = __halves2half2(__float2half_rn(v.z), __float2half_rn(v.w));
    *(uint2*)(out + (size_t)i * 4) = make_uint2(*(uint32_t*)&a, *(uint32_t*)&b);
}

// tiled weight transpose-cast: W1 [384,256] -> w1a/w1b, W2 [256,256] -> w2t
__global__ __launch_bounds__(256) void cast_w_tiled(
    const float* __restrict__ W1, const float* __restrict__ W2,
    __half* __restrict__ w1a, __half* __restrict__ w1b, __half* __restrict__ w2t)
{
    __shared__ float tile[32][33];
    const int tb = blockIdx.x;            // 0..159 (96 for W1, 64 for W2)
    const int tid = threadIdx.x;
    const float* W; int k0, n0; bool isW1;
    if (tb < 96) { W = W1; k0 = (tb >> 3) * 32; n0 = (tb & 7) * 32; isW1 = true; }
    else { int u = tb - 96; W = W2; k0 = (u >> 3) * 32; n0 = (u & 7) * 32; isW1 = false; }

    const int tr = tid >> 5, tc = tid & 31;
    #pragma unroll
    for (int i = 0; i < 4; i++)
        tile[tr + 8 * i][tc] = W[(size_t)(k0 + tr + 8 * i) * C_HID + n0 + tc];
    __syncthreads();

    const int ln = tid >> 3;              // 0..31
    const int kq = (tid & 7) * 4;         // 0,4,..28
    const int n = n0 + ln;
    __half h[4];
    #pragma unroll
    for (int j = 0; j < 4; j++)
        h[j] = __float2half_rn(tile[kq + j][ln]);
    __half* o; int K, k;
    if (isW1) {
        if (k0 < C_IN) { K = C_IN;  k = k0 + kq;          o = w1a + (size_t)n * K; }
        else           { K = C_SKIP; k = k0 - C_IN + kq;  o = w1b + (size_t)n * K; }
    } else             { K = C_HID; k = k0 + kq;          o = w2t + (size_t)n * K; }
    *(uint2*)&o[k] = *(uint2*)h;
}

// ---------------- smem layout -------------------------------------------------
#define PITCH 40                        // fp16 per smem row (80B)
#define CH_BYTES (128 * PITCH * 2)      // 10240 per 32-k chunk per operand
#define SMEM_H1   0                     // 8 chunks * 10240 = 81920 (fused path)
#define SMEM_G2ST 40960                 // 2 stages * 20480 (overlays H1 chunks 4-7)
#define SMEM_G3B  81920                 // 3 B-only stages * 10240 = 30720
#define SM_BYTES  112640

// ---------------- G1 tile: y = xh @ w1a^T -> fp16 yh (4-stage, 8 chunks) ----
__device__ __forceinline__ void gemm_g1(
    const __half* __restrict__ A, const __half* __restrict__ Bw,
    __half* __restrict__ outh, int row0, int col0, char* smem, uint32_t sb)
{
    const int tid = threadIdx.x;
    const int wid = tid >> 5, lane = tid & 31;
    const int g = lane >> 2, t = lane & 3;
    const int wm = wid & 3, wn = wid >> 2;

    const int lrow = tid >> 1;
    const int lch  = (tid & 1) * 2;
    const uint32_t dA0 = sb + (uint32_t)(lrow * 80 + lch * 16);
    const uint32_t dB0 = dA0 + CH_BYTES;
    const __half* gA = A + (size_t)(row0 + lrow) * C_IN + lch * 8;
    const __half* gB = Bw + (size_t)(col0 + lrow) * C_IN + lch * 8;

    uint32_t aAddr[2], bAddr[4];
    #pragma unroll
    for (int mt = 0; mt < 2; mt++)
        aAddr[mt] = sb + (uint32_t)(((wm * 32 + mt * 16 + (lane & 15)) * PITCH
                                     + (lane >> 4) * 8) * 2);
    #pragma unroll
    for (int p = 0; p < 4; p++)
        bAddr[p] = sb + CH_BYTES + (uint32_t)(((wn * 64 + p * 16 + (lane & 7)
                                     + ((lane >> 4) & 1) * 8) * PITCH
                                     + ((lane >> 3) & 1) * 8) * 2);

    float acc[2][8][4];
    #pragma unroll
    for (int mt = 0; mt < 2; mt++)
        #pragma unroll
        for (int nt = 0; nt < 8; nt++)
            #pragma unroll
            for (int e = 0; e < 4; e++) acc[mt][nt][e] = 0.f;

    #pragma unroll
    for (int s = 0; s < 3; s++) {
        const uint32_t o = s * 20480;
        cp16(dA0 + o, gA + s * 32); cp16(dA0 + o + 16, gA + s * 32 + 8);
        cp16(dB0 + o, gB + s * 32); cp16(dB0 + o + 16, gB + s * 32 + 8);
        CP_COMMIT();
    }

    #pragma unroll
    for (int c = 0; c < 8; c++) {
        if (c + 3 <= 8)      { CP_WAIT(2); }
        else if (c + 2 == 8) { CP_WAIT(1); }
        else                 { CP_WAIT(0); }
        __syncthreads();

        if (c + 3 < 8) {
            const int c2 = c + 3;
            const uint32_t o = (c2 & 3) * 20480;
            cp16(dA0 + o, gA + c2 * 32); cp16(dA0 + o + 16, gA + c2 * 32 + 8);
            cp16(dB0 + o, gB + c2 * 32); cp16(dB0 + o + 16, gB + c2 * 32 + 8);
            CP_COMMIT();
        }

        const uint32_t so = (c & 3) * 20480;
        #pragma unroll
        for (int ks = 0; ks < 2; ks++) {
            const uint32_t ko = so + ks * 32;
            uint32_t a[2][4], bq[4][4];
            LDSM4(a[0], aAddr[0] + ko);
            LDSM4(a[1], aAddr[1] + ko);
            LDSM4(bq[0], bAddr[0] + ko);
            LDSM4(bq[1], bAddr[1] + ko);
            LDSM4(bq[2], bAddr[2] + ko);
            LDSM4(bq[3], bAddr[3] + ko);
            #pragma unroll
            for (int mt = 0; mt < 2; mt++)
                #pragma unroll
                for (int nt = 0; nt < 8; nt++)
                    mma16816(acc[mt][nt], a[mt], &bq[nt >> 1][(nt & 1) * 2]);
        }
    }

    #pragma unroll
    for (int mt = 0; mt < 2; mt++)
        #pragma unroll
        for (int half = 0; half < 2; half++) {
            const int r = row0 + wm * 32 + mt * 16 + g + half * 8;
            #pragma unroll
            for (int nt = 0; nt < 8; nt++) {
                const int ccol = col0 + wn * 64 + nt * 8 + 2 * t;
                __half2 h2 = __halves2half2(
                    __float2half_rn(acc[mt][nt][half * 2 + 0]),
                    __float2half_rn(acc[mt][nt][half * 2 + 1]));
                *(__half2*)&outh[(size_t)r * C_HID + ccol] = h2;
            }
        }
}

// ---------------- G2 phase: h1 col-tile -> smem H1 chunks (2-stage, 4 chunks)
__device__ __forceinline__ void g2_phase(
    char* smem, uint32_t sb,
    const __half* __restrict__ xsh, const __half* __restrict__ w1b,
    const float* __restrict__ b1, const __half* __restrict__ yh,
    const int* __restrict__ gidx, const float* __restrict__ gw,
    const int* flags, int cloud, bool do_wait,
    int row0, int bx)
{
    const int tid = threadIdx.x;
    const int wid = tid >> 5, lane = tid & 31;
    const int g = lane >> 2, t = lane & 3;
    const int wm = wid & 3, wn = wid >> 2;

    const int lrow = tid >> 1;
    const int lch  = (tid & 1) * 2;
    const uint32_t stA = sb + SMEM_G2ST + (uint32_t)(lrow * 80 + lch * 16);
    const uint32_t stB = stA + CH_BYTES;
    const __half* gA = xsh + (size_t)(row0 + lrow) * C_SKIP + lch * 8;
    const __half* gB = w1b + (size_t)(bx * 128 + lrow) * C_SKIP + lch * 8;

    uint32_t aAddr[2], bAddr[4];
    #pragma unroll
    for (int mt = 0; mt < 2; mt++)
        aAddr[mt] = sb + SMEM_G2ST + (uint32_t)(((wm * 32 + mt * 16 + (lane & 15)) * PITCH
                                     + (lane >> 4) * 8) * 2);
    #pragma unroll
    for (int p = 0; p < 4; p++)
        bAddr[p] = sb + SMEM_G2ST + CH_BYTES + (uint32_t)(((wn * 64 + p * 16 + (lane & 7)
                                     + ((lane >> 4) & 1) * 8) * PITCH
                                     + ((lane >> 3) & 1) * 8) * 2);

    float acc[2][8][4];
    #pragma unroll
    for (int mt = 0; mt < 2; mt++)
        #pragma unroll
        for (int nt = 0; nt < 8; nt++)
            #pragma unroll
            for (int e = 0; e < 4; e++) acc[mt][nt][e] = 0.f;

    cp16(stA, gA); cp16(stA + 16, gA + 8);
    cp16(stB, gB); cp16(stB + 16, gB + 8);
    CP_COMMIT();

    #pragma unroll
    for (int c = 0; c < 4; c++) {
        CP_WAIT(0);
        __syncthreads();
        if (c + 1 < 4) {
            const uint32_t o = ((c + 1) & 1) * 20480;
            cp16(stA + o, gA + (c + 1) * 32); cp16(stA + o + 16, gA + (c + 1) * 32 + 8);
            cp16(stB + o, gB + (c + 1) * 32); cp16(stB + o + 16, gB + (c + 1) * 32 + 8);
            CP_COMMIT();
        }
        const uint32_t so = (c & 1) * 20480;
        #pragma unroll
        for (int ks = 0; ks < 2; ks++) {
            const uint32_t ko = so + ks * 32;
            uint32_t a[2][4], bq[4][4];
            LDSM4(a[0], aAddr[0] + ko);
            LDSM4(a[1], aAddr[1] + ko);
            LDSM4(bq[0], bAddr[0] + ko);
            LDSM4(bq[1], bAddr[1] + ko);
            LDSM4(bq[2], bAddr[2] + ko);
            LDSM4(bq[3], bAddr[3] + ko);
            #pragma unroll
            for (int mt = 0; mt < 2; mt++)
                #pragma unroll
                for (int nt = 0; nt < 8; nt++)
                    mma16816(acc[mt][nt], a[mt], &bq[nt >> 1][(nt & 1) * 2]);
        }
    }
    __syncthreads();   // all warps done reading stages before epilogue overwrites

    if (do_wait) {
        if (tid == 0) {
            volatile int* vf = (volatile int*)flags;
            while (vf[0] < BATCH * (N_FINE / 128)) __nanosleep(100);
            while (vf[1 + cloud] < 16) __nanosleep(100);
        }
        __syncthreads();
        __threadfence();
    }

    // epilogue: bias + y-gather + relu -> smem H1 chunks (stage layout)
    #pragma unroll
    for (int mt = 0; mt < 2; mt++)
        #pragma unroll
        for (int half = 0; half < 2; half++) {
            const int r2 = wm * 32 + mt * 16 + g + half * 8;
            const int r = row0 + r2;
            const int i0 = gidx[r * 3 + 0], i1 = gidx[r * 3 + 1], i2 = gidx[r * 3 + 2];
            const float w0 = gw[r * 3 + 0], w1 = gw[r * 3 + 1], w2 = gw[r * 3 + 2];
            #pragma unroll
            for (int nt = 0; nt < 8; nt++) {
                const int ccol = wn * 64 + nt * 8 + 2 * t;
                const int gcol = bx * 128 + ccol;
                float vx = acc[mt][nt][half * 2 + 0];
                float vy = acc[mt][nt][half * 2 + 1];
                float2 bb = *(const float2*)&b1[gcol];
                float2 y0 = __half22float2(*(const __half2*)&yh[(size_t)i0 * C_HID + gcol]);
                float2 y1 = __half22float2(*(const __half2*)&yh[(size_t)i1 * C_HID + gcol]);
                float2 y2 = __half22float2(*(const __half2*)&yh[(size_t)i2 * C_HID + gcol]);
                vx = fmaxf(vx + bb.x + w0 * y0.x + w1 * y1.x + w2 * y2.x, 0.f);
                vy = fmaxf(vy + bb.y + w0 * y0.y + w1 * y1.y + w2 * y2.y, 0.f);
                __half2 h2 = __halves2half2(__float2half_rn(vx), __float2half_rn(vy));
                const uint32_t off = (uint32_t)((bx * 4 + (ccol >> 5)) * CH_BYTES
                                                + r2 * 80 + (ccol & 31) * 2);
                *(__half2*)(smem + off) = h2;
            }
        }
    __syncthreads();
}

// ---------------- G3 phase: out col-tile from smem h1 (3-stage B, 8 chunks) -
__device__ __forceinline__ void g3_phase(
    char* smem, uint32_t sb,
    const __half* __restrict__ w2t, const float* __restrict__ b2,
    float* __restrict__ outp, int row0, int bxx)
{
    const int tid = threadIdx.x;
    const int wid = tid >> 5, lane = tid & 31;
    const int g = lane >> 2, t = lane & 3;
    const int wm = wid & 3, wn = wid >> 2;

    const int lrow = tid >> 1;
    const int lch  = (tid & 1) * 2;
    const uint32_t stB = sb + SMEM_G3B + (uint32_t)(lrow * 80 + lch * 16);
    const __half* gB = w2t + (size_t)(bxx * 128 + lrow) * C_HID + lch * 8;

    uint32_t aAddr[2], bAddr[4];
    #pragma unroll
    for (int mt = 0; mt < 2; mt++)
        aAddr[mt] = sb + (uint32_t)(((wm * 32 + mt * 16 + (lane & 15)) * PITCH
                                     + (lane >> 4) * 8) * 2);
    #pragma unroll
    for (int p = 0; p < 4; p++)
        bAddr[p] = sb + SMEM_G3B + (uint32_t)(((wn * 64 + p * 16 + (lane & 7)
                                     + ((lane >> 4) & 1) * 8) * PITCH
                                     + ((lane >> 3) & 1) * 8) * 2);

    float acc[2][8][4];
    #pragma unroll
    for (int mt = 0; mt < 2; mt++)
        #pragma unroll
        for (int nt = 0; nt < 8; nt++)
            #pragma unroll
            for (int e = 0; e < 4; e++) acc[mt][nt][e] = 0.f;

    __syncthreads();   // h1 writes / prior B-stage readers complete

    #pragma unroll
    for (int s = 0; s < 2; s++) {
        const uint32_t o = s * CH_BYTES;
        cp16(stB + o, gB + s * 32); cp16(stB + o + 16, gB + s * 32 + 8);
        CP_COMMIT();
    }

    #pragma unroll
    for (int c = 0; c < 8; c++) {
        if (c + 1 < 8) { CP_WAIT(1); } else { CP_WAIT(0); }
        __syncthreads();
        if (c + 2 < 8) {
            const int c2 = c + 2;
            const uint32_t o = (c2 % 3) * CH_BYTES;
            cp16(stB + o, gB + c2 * 32); cp16(stB + o + 16, gB + c2 * 32 + 8);
            CP_COMMIT();
        }
        #pragma unroll
        for (int ks = 0; ks < 2; ks++) {
            const uint32_t koA = c * CH_BYTES + ks * 32;
            const uint32_t koB = (c % 3) * CH_BYTES + ks * 32;
            uint32_t a[2][4], bq[4][4];
            LDSM4(a[0], aAddr[0] + koA);
            LDSM4(a[1], aAddr[1] + koA);
            LDSM4(bq[0], bAddr[0] + koB);
            LDSM4(bq[1], bAddr[1] + koB);
            LDSM4(bq[2], bAddr[2] + koB);
            LDSM4(bq[3], bAddr[3] + koB);
            #pragma unroll
            for (int mt = 0; mt < 2; mt++)
                #pragma unroll
                for (int nt = 0; nt < 8; nt++)
                    mma16816(acc[mt][nt], a[mt], &bq[nt >> 1][(nt & 1) * 2]);
        }
    }

    // epilogue: bias + relu -> fp32 out
    #pragma unroll
    for (int mt = 0; mt < 2; mt++)
        #pragma unroll
        for (int half = 0; half < 2; half++) {
            const int r = row0 + wm * 32 + mt * 16 + g + half * 8;
            #pragma unroll
            for (int nt = 0; nt < 8; nt++) {
                const int ccol = wn * 64 + nt * 8 + 2 * t;
                const int gcol = bxx * 128 + ccol;
                float2 bb = *(const float2*)&b2[gcol];
                float vx = fmaxf(acc[mt][nt][half * 2 + 0] + bb.x, 0.f);
                float vy = fmaxf(acc[mt][nt][half * 2 + 1] + bb.y, 0.f);
                *(float2*)&outp[(size_t)r * C_HID + gcol] = make_float2(vx, vy);
            }
        }
}

// ---------------- mega kernel: G1 (256) + fused G2+G3 (512) -----------------
#define G1_TILES 256
#define FUSED_TILES 512

__global__ __launch_bounds__(256, 2) void mega_gemm(
    const __half* __restrict__ xh, const __half* __restrict__ xsh,
    const __half* __restrict__ w1a, const __half* __restrict__ w1b,
    const __half* __restrict__ w2t,
    const float* __restrict__ b1, const float* __restrict__ b2,
    __half* __restrict__ yh, float* __restrict__ outp,
    const int* __restrict__ gidx, const float* __restrict__ gw,
    int* __restrict__ flags)
{
    extern __shared__ __align__(16) char smem[];
    const uint32_t sb = smem_u32(smem);
    const int t = blockIdx.x;
    const int tid = threadIdx.x;

    if (t < G1_TILES) {
        const int bx = t & 1, by = t >> 1;
        gemm_g1(xh, w1a, yh, by * 128, bx * 128, smem, sb);
        __threadfence();
        __syncthreads();
        if (tid == 0) atomicAdd(&flags[1 + (by >> 3)], 1);
    } else {
        const int u = t - G1_TILES;           // row block 0..511
        const int row0 = u * 128;
        const int cloud = u >> 5;
        g2_phase(smem, sb, xsh, w1b, b1, yh, gidx, gw, flags, cloud, true,  row0, 0);
        g2_phase(smem, sb, xsh, w1b, b1, yh, gidx, gw, flags, cloud, false, row0, 1);
        g3_phase(smem, sb, w2t, b2, outp, row0, 0);
        g3_phase(smem, sb, w2t, b2, outp, row0, 1);
    }
}

// batch_skip int32 -> float (tuple tail)
__global__ void cast_batch_kernel(const int* __restrict__ b, float* __restrict__ out, int n)
{
    int i = blockIdx.x * blockDim.x + threadIdx.x;
    if (i < n) out[i] = (float)b[i];
}

// ---------------------------------------------------------------------------
extern "C" void kernel_launch(void* const* d_in, const int* in_sizes, int n_in,
                              void* d_out, int out_size)
{
    (void)in_sizes; (void)n_in;
    const float* x        = (const float*)d_in[0];
    const float* pos      = (const float*)d_in[1];
    const float* x_skip   = (const float*)d_in[2];
    const float* pos_skip = (const float*)d_in[3];
    const float* W1       = (const float*)d_in[4];
    const float* b1       = (const float*)d_in[5];
    const float* W2       = (const float*)d_in[6];
    const float* b2       = (const float*)d_in[7];

    float* w; int *idx, *flags;
    __half *yh, *xh, *xsh, *w1a, *w1b, *w2t;
    cudaGetSymbolAddress((void**)&yh,    g_yh);
    cudaGetSymbolAddress((void**)&idx,   g_idx);
    cudaGetSymbolAddress((void**)&w,     g_w);
    cudaGetSymbolAddress((void**)&xh,    g_xh);
    cudaGetSymbolAddress((void**)&xsh,   g_xsh);
    cudaGetSymbolAddress((void**)&w1a,   g_w1a);
    cudaGetSymbolAddress((void**)&w1b,   g_w1b);
    cudaGetSymbolAddress((void**)&w2t,   g_w2t);
    cudaGetSymbolAddress((void**)&flags, g_flags);

    static bool init_done = false;
    static cudaStream_t s_knn, s_aux;
    static cudaEvent_t ev_fork, ev_knn, ev_aux, ev_tail;
    if (!init_done) {
        cudaFuncSetAttribute(mega_gemm, cudaFuncAttributeMaxDynamicSharedMemorySize, SM_BYTES);
        cudaStreamCreateWithFlags(&s_knn, cudaStreamNonBlocking);
        cudaStreamCreateWithFlags(&s_aux, cudaStreamNonBlocking);
        cudaEventCreateWithFlags(&ev_fork, cudaEventDisableTiming);
        cudaEventCreateWithFlags(&ev_knn, cudaEventDisableTiming);
        cudaEventCreateWithFlags(&ev_aux, cudaEventDisableTiming);
        cudaEventCreateWithFlags(&ev_tail, cudaEventDisableTiming);
        init_done = true;
    }

    const long long H_ELEMS   = (long long)NF_TOT * C_HID;
    const long long POS_ELEMS = (long long)NF_TOT * 3;

    // reset flags BEFORE forking knn (knn increments flags[0])
    cudaMemsetAsync(flags, 0, 64 * sizeof(int), 0);
    cudaEventRecord(ev_fork, 0);

    // side stream 1: kNN (self-signals via flags[0])
    cudaStreamWaitEvent(s_knn, ev_fork, 0);
    knn_kernel<<<BATCH * (N_FINE / 128), 128, 0, s_knn>>>(pos, pos_skip, idx, w, flags);
    cudaEventRecord(ev_knn, s_knn);

    // side stream 2: weight cast + xsh cast (mega deps), then tuple-tail ops
    cudaStreamWaitEvent(s_aux, ev_fork, 0);
    cast_w_tiled<<<160, 256, 0, s_aux>>>(W1, W2, w1a, w1b, w2t);
    cast_act<<<(NF_TOT * C_SKIP / 4 + 255) / 256, 256, 0, s_aux>>>(
        x_skip, xsh, NF_TOT * C_SKIP / 4);
    cudaEventRecord(ev_aux, s_aux);
    // tuple tail (independent of mega; overlaps it)
    if ((long long)out_size >= H_ELEMS + POS_ELEMS) {
        cudaMemcpyAsync((float*)d_out + H_ELEMS, pos_skip,
                        POS_ELEMS * sizeof(float), cudaMemcpyDeviceToDevice, s_aux);
    }
    if ((long long)out_size >= H_ELEMS + POS_ELEMS + NF_TOT) {
        const int* batch_skip = (const int*)d_in[9];
        cast_batch_kernel<<<(NF_TOT + 255) / 256, 256, 0, s_aux>>>(
            batch_skip, (float*)d_out + H_ELEMS + POS_ELEMS, NF_TOT);
    }

    // main stream: xh cast only, then mega
    cast_act<<<(NC_TOT * C_IN / 4 + 255) / 256, 256>>>(x, xh, NC_TOT * C_IN / 4);

    cudaStreamWaitEvent(0, ev_aux, 0);
    mega_gemm<<<G1_TILES + FUSED_TILES, 256, SM_BYTES>>>(
        xh, xsh, w1a, w1b, w2t, b1, b2,
        yh, (float*)d_out, idx, w, flags);

    // join side streams for graph completeness
    cudaStreamWaitEvent(0, ev_knn, 0);
    cudaEventRecord(ev_tail, s_aux);
    cudaStreamWaitEvent(0, ev_tail, 0);
}

// round 15
// speedup vs baseline: 1.2570x; 1.0018x over previous
#include <cuda_runtime.h>
#include <cuda_fp16.h>
#include <cstdint>

#define BATCH    16
#define N_COARSE 1024
#define N_FINE   4096
#define C_IN     256
#define C_SKIP   128
#define C_HID    256
#define NC_TOT   (BATCH * N_COARSE)   // 16384
#define NF_TOT   (BATCH * N_FINE)     // 65536

// ---------------- scratch (static device globals; no runtime alloc) --------
__device__ __half  g_yh[NC_TOT * C_HID];                // 8 MB fp16
__device__ int     g_idx[NF_TOT * 3];
__device__ float   g_w[NF_TOT * 3];
__device__ __half  g_xh[NC_TOT * C_IN];                 // [16384, 256] fp16
__device__ __half  g_xsh[NF_TOT * C_SKIP];              // [65536, 128] fp16
__device__ __half  g_w1a[C_HID * C_IN];                 // [256 n, 256 k] (W1a^T)
__device__ __half  g_w1b[C_HID * C_SKIP];               // [256 n, 128 k] (W1b^T)
__device__ __half  g_w2t[C_HID * C_HID];                // [256 n, 256 k] (W2^T)
// flags: [1..16]=per-cloud G1 tile counter (16 each), [17..32]=per-cloud knn counter (32 each)
__device__ int     g_flags[64];

// ---------------- PTX helpers (portable, no arch-gated features) -----------
__device__ __forceinline__ uint32_t smem_u32(const void* p) {
    return (uint32_t)__cvta_generic_to_shared(p);
}
__device__ __forceinline__ void cp16(uint32_t dst, const void* src) {
    asm volatile("cp.async.cg.shared.global [%0], [%1], 16;" :: "r"(dst), "l"(src));
}
#define CP_COMMIT()  asm volatile("cp.async.commit_group;" ::: "memory")
#define CP_WAIT(n)   asm volatile("cp.async.wait_group %0;" :: "n"(n) : "memory")
#define LDSM4(r, addr) \
    asm volatile("ldmatrix.sync.aligned.m8n8.x4.shared.b16 {%0,%1,%2,%3}, [%4];" \
        : "=r"((r)[0]), "=r"((r)[1]), "=r"((r)[2]), "=r"((r)[3]) : "r"(addr))

__device__ __forceinline__ void mma16816(float* c, const uint32_t* a, const uint32_t* b) {
    asm volatile(
        "mma.sync.aligned.m16n8k16.row.col.f32.f16.f16.f32 "
        "{%0,%1,%2,%3}, {%4,%5,%6,%7}, {%8,%9}, {%0,%1,%2,%3};"
        : "+f"(c[0]), "+f"(c[1]), "+f"(c[2]), "+f"(c[3])
        : "r"(a[0]), "r"(a[1]), "r"(a[2]), "r"(a[3]), "r"(b[0]), "r"(b[1]));
}

// ---------------- kNN (k=3): 1 point/thread, float4 smem, per-cloud signal --
__global__ __launch_bounds__(128) void knn_kernel(
    const float* __restrict__ pos, const float* __restrict__ pos_skip,
    int* __restrict__ gidx, float* __restrict__ gw, int* __restrict__ flags)
{
    __shared__ float4 sp[N_COARSE];   // 16 KB
    const int chunks = N_FINE / 128;              // 32
    const int b = blockIdx.x / chunks;
    const int chunk = blockIdx.x % chunks;
    const int tid = threadIdx.x;

    const float* pc = pos + (size_t)b * N_COARSE * 3;
    for (int i = tid; i < N_COARSE; i += 128)
        sp[i] = make_float4(pc[i * 3 + 0], pc[i * 3 + 1], pc[i * 3 + 2], 0.f);
    __syncthreads();

    const int f = b * N_FINE + chunk * 128 + tid;
    const float px = pos_skip[f * 3 + 0];
    const float py = pos_skip[f * 3 + 1];
    const float pz = pos_skip[f * 3 + 2];

    float d0 = 3.4e38f, d1 = 3.4e38f, d2 = 3.4e38f;
    int i0 = 0, i1 = 0, i2 = 0;
    #pragma unroll 4
    for (int j = 0; j < N_COARSE; j++) {
        float4 p = sp[j];
        float dx = px - p.x, dy = py - p.y, dz = pz - p.z;
        float d = dx * dx + dy * dy + dz * dz;
        if (d < d2) {
            if (d < d1) {
                d2 = d1; i2 = i1;
                if (d < d0) { d1 = d0; i1 = i0; d0 = d; i0 = j; }
                else        { d1 = d;  i1 = j; }
            } else { d2 = d; i2 = j; }
        }
    }
    float w0 = 1.0f / fmaxf(d0, 1e-16f);
    float w1 = 1.0f / fmaxf(d1, 1e-16f);
    float w2 = 1.0f / fmaxf(d2, 1e-16f);
    float inv = 1.0f / (w0 + w1 + w2);
    gidx[f * 3 + 0] = b * N_COARSE + i0;
    gidx[f * 3 + 1] = b * N_COARSE + i1;
    gidx[f * 3 + 2] = b * N_COARSE + i2;
    gw[f * 3 + 0] = w0 * inv;
    gw[f * 3 + 1] = w1 * inv;
    gw[f * 3 + 2] = w2 * inv;

    __threadfence();
    __syncthreads();
    if (tid == 0) atomicAdd(&flags[17 + b], 1);
}

// ---------------- casts ------------------------------------------------------
__global__ void cast_act(const float* __restrict__ in, __half* __restrict__ out, int n4)
{
    int i = blockIdx.x * blockDim.x + threadIdx.x;
    if (i >= n4) return;
    float4 v = *(const float4*)(in + (size_t)i * 4);
    __half2 a = __halves2half2(__float2half_rn(v.x), __float2half_rn(v.y));
    __half2 b = __halves2half2(__float2half_rn(v.z), __float2half_rn(v.w));
    *(uint2*)(out + (size_t)i * 4) = make_uint2(*(uint32_t*)&a, *(uint32_t*)&b);
}

// tiled weight transpose-cast: W1 [384,256] -> w1a/w1b, W2 [256,256] -> w2t
__global__ __launch_bounds__(256) void cast_w_tiled(
    const float* __restrict__ W1, const float* __restrict__ W2,
    __half* __restrict__ w1a, __half* __restrict__ w1b, __half* __restrict__ w2t)
{
    __shared__ float tile[32][33];
    const int tb = blockIdx.x;            // 0..159 (96 for W1, 64 for W2)
    const int tid = threadIdx.x;
    const float* W; int k0, n0; bool isW1;
    if (tb < 96) { W = W1; k0 = (tb >> 3) * 32; n0 = (tb & 7) * 32; isW1 = true; }
    else { int u = tb - 96; W = W2; k0 = (u >> 3) * 32; n0 = (u & 7) * 32; isW1 = false; }

    const int tr = tid >> 5, tc = tid & 31;
    #pragma unroll
    for (int i = 0; i < 4; i++)
        tile[tr + 8 * i][tc] = W[(size_t)(k0 + tr + 8 * i) * C_HID + n0 + tc];
    __syncthreads();

    const int ln = tid >> 3;              // 0..31
    const int kq = (tid & 7) * 4;         // 0,4,..28
    const int n = n0 + ln;
    __half h[4];
    #pragma unroll
    for (int j = 0; j < 4; j++)
        h[j] = __float2half_rn(tile[kq + j][ln]);
    __half* o; int K, k;
    if (isW1) {
        if (k0 < C_IN) { K = C_IN;  k = k0 + kq;          o = w1a + (size_t)n * K; }
        else           { K = C_SKIP; k = k0 - C_IN + kq;  o = w1b + (size_t)n * K; }
    } else             { K = C_HID; k = k0 + kq;          o = w2t + (size_t)n * K; }
    *(uint2*)&o[k] = *(uint2*)h;
}

// ---------------- smem layout -------------------------------------------------
#define PITCH 40                        // fp16 per smem row (80B)
#define CH_BYTES (128 * PITCH * 2)      // 10240 per 32-k chunk per operand
#define SMEM_H1   0                     // 8 chunks * 10240 = 81920 (fused path)
#define SMEM_A2   40960                 // resident G2 A-tile, 4 chunks (overlays H1 4-7)
#define SMEM_B2   81920                 // G2 B double-buffer, 2 * 10240
#define SMEM_G3B  81920                 // G3 B 3-stage region (same region, later phase)
#define SM_BYTES  112640

// ---------------- G1 tile: y = xh @ w1a^T -> fp16 yh (4-stage, 8 chunks) ----
__device__ __forceinline__ void gemm_g1(
    const __half* __restrict__ A, const __half* __restrict__ Bw,
    __half* __restrict__ outh, int row0, int col0, char* smem, uint32_t sb)
{
    const int tid = threadIdx.x;
    const int wid = tid >> 5, lane = tid & 31;
    const int g = lane >> 2, t = lane & 3;
    const int wm = wid & 3, wn = wid >> 2;

    const int lrow = tid >> 1;
    const int lch  = (tid & 1) * 2;
    const uint32_t dA0 = sb + (uint32_t)(lrow * 80 + lch * 16);
    const uint32_t dB0 = dA0 + CH_BYTES;
    const __half* gA = A + (size_t)(row0 + lrow) * C_IN + lch * 8;
    const __half* gB = Bw + (size_t)(col0 + lrow) * C_IN + lch * 8;

    uint32_t aAddr[2], bAddr[4];
    #pragma unroll
    for (int mt = 0; mt < 2; mt++)
        aAddr[mt] = sb + (uint32_t)(((wm * 32 + mt * 16 + (lane & 15)) * PITCH
                                     + (lane >> 4) * 8) * 2);
    #pragma unroll
    for (int p = 0; p < 4; p++)
        bAddr[p] = sb + CH_BYTES + (uint32_t)(((wn * 64 + p * 16 + (lane & 7)
                                     + ((lane >> 4) & 1) * 8) * PITCH
                                     + ((lane >> 3) & 1) * 8) * 2);

    float acc[2][8][4];
    #pragma unroll
    for (int mt = 0; mt < 2; mt++)
        #pragma unroll
        for (int nt = 0; nt < 8; nt++)
            #pragma unroll
            for (int e = 0; e < 4; e++) acc[mt][nt][e] = 0.f;

    #pragma unroll
    for (int s = 0; s < 3; s++) {
        const uint32_t o = s * 20480;
        cp16(dA0 + o, gA + s * 32); cp16(dA0 + o + 16, gA + s * 32 + 8);
        cp16(dB0 + o, gB + s * 32); cp16(dB0 + o + 16, gB + s * 32 + 8);
        CP_COMMIT();
    }

    #pragma unroll
    for (int c = 0; c < 8; c++) {
        if (c + 3 <= 8)      { CP_WAIT(2); }
        else if (c + 2 == 8) { CP_WAIT(1); }
        else                 { CP_WAIT(0); }
        __syncthreads();

        if (c + 3 < 8) {
            const int c2 = c + 3;
            const uint32_t o = (c2 & 3) * 20480;
            cp16(dA0 + o, gA + c2 * 32); cp16(dA0 + o + 16, gA + c2 * 32 + 8);
            cp16(dB0 + o, gB + c2 * 32); cp16(dB0 + o + 16, gB + c2 * 32 + 8);
            CP_COMMIT();
        }

        const uint32_t so = (c & 3) * 20480;
        #pragma unroll
        for (int ks = 0; ks < 2; ks++) {
            const uint32_t ko = so + ks * 32;
            uint32_t a[2][4], bq[4][4];
            LDSM4(a[0], aAddr[0] + ko);
            LDSM4(a[1], aAddr[1] + ko);
            LDSM4(bq[0], bAddr[0] + ko);
            LDSM4(bq[1], bAddr[1] + ko);
            LDSM4(bq[2], bAddr[2] + ko);
            LDSM4(bq[3], bAddr[3] + ko);
            #pragma unroll
            for (int mt = 0; mt < 2; mt++)
                #pragma unroll
                for (int nt = 0; nt < 8; nt++)
                    mma16816(acc[mt][nt], a[mt], &bq[nt >> 1][(nt & 1) * 2]);
        }
    }

    #pragma unroll
    for (int mt = 0; mt < 2; mt++)
        #pragma unroll
        for (int half = 0; half < 2; half++) {
            const int r = row0 + wm * 32 + mt * 16 + g + half * 8;
            #pragma unroll
            for (int nt = 0; nt < 8; nt++) {
                const int ccol = col0 + wn * 64 + nt * 8 + 2 * t;
                __half2 h2 = __halves2half2(
                    __float2half_rn(acc[mt][nt][half * 2 + 0]),
                    __float2half_rn(acc[mt][nt][half * 2 + 1]));
                *(__half2*)&outh[(size_t)r * C_HID + ccol] = h2;
            }
        }
}

// ---------------- G2 phase: h1 col-tile -> smem H1 chunks -------------------
// A (xsh row-tile) resident at SMEM_A2 (loaded when load_a); B double-buffered.
__device__ __forceinline__ void g2_phase(
    char* smem, uint32_t sb, bool load_a,
    const __half* __restrict__ xsh, const __half* __restrict__ w1b,
    const float* __restrict__ b1, const __half* __restrict__ yh,
    const int* __restrict__ gidx, const float* __restrict__ gw,
    const int* flags, int cloud, bool do_wait,
    int row0, int bx)
{
    const int tid = threadIdx.x;
    const int wid = tid >> 5, lane = tid & 31;
    const int g = lane >> 2, t = lane & 3;
    const int wm = wid & 3, wn = wid >> 2;

    const int lrow = tid >> 1;
    const int lch  = (tid & 1) * 2;
    const uint32_t stA = sb + SMEM_A2 + (uint32_t)(lrow * 80 + lch * 16);
    const uint32_t stB = sb + SMEM_B2 + (uint32_t)(lrow * 80 + lch * 16);
    const __half* gA = xsh + (size_t)(row0 + lrow) * C_SKIP + lch * 8;
    const __half* gB = w1b + (size_t)(bx * 128 + lrow) * C_SKIP + lch * 8;

    uint32_t aAddr[2], bAddr[4];
    #pragma unroll
    for (int mt = 0; mt < 2; mt++)
        aAddr[mt] = sb + SMEM_A2 + (uint32_t)(((wm * 32 + mt * 16 + (lane & 15)) * PITCH
                                     + (lane >> 4) * 8) * 2);
    #pragma unroll
    for (int p = 0; p < 4; p++)
        bAddr[p] = sb + SMEM_B2 + (uint32_t)(((wn * 64 + p * 16 + (lane & 7)
                                     + ((lane >> 4) & 1) * 8) * PITCH
                                     + ((lane >> 3) & 1) * 8) * 2);

    float acc[2][8][4];
    #pragma unroll
    for (int mt = 0; mt < 2; mt++)
        #pragma unroll
        for (int nt = 0; nt < 8; nt++)
            #pragma unroll
            for (int e = 0; e < 4; e++) acc[mt][nt][e] = 0.f;

    if (load_a) {
        #pragma unroll
        for (int c = 0; c < 4; c++) {
            cp16(stA + c * CH_BYTES, gA + c * 32);
            cp16(stA + c * CH_BYTES + 16, gA + c * 32 + 8);
        }
    }
    cp16(stB, gB); cp16(stB + 16, gB + 8);
    CP_COMMIT();

    #pragma unroll
    for (int c = 0; c < 4; c++) {
        CP_WAIT(0);
        __syncthreads();
        if (c + 1 < 4) {
            const uint32_t o = ((c + 1) & 1) * CH_BYTES;
            cp16(stB + o, gB + (c + 1) * 32);
            cp16(stB + o + 16, gB + (c + 1) * 32 + 8);
            CP_COMMIT();
        }
        #pragma unroll
        for (int ks = 0; ks < 2; ks++) {
            const uint32_t koA = c * CH_BYTES + ks * 32;
            const uint32_t koB = (c & 1) * CH_BYTES + ks * 32;
            uint32_t a[2][4], bq[4][4];
            LDSM4(a[0], aAddr[0] + koA);
            LDSM4(a[1], aAddr[1] + koA);
            LDSM4(bq[0], bAddr[0] + koB);
            LDSM4(bq[1], bAddr[1] + koB);
            LDSM4(bq[2], bAddr[2] + koB);
            LDSM4(bq[3], bAddr[3] + koB);
            #pragma unroll
            for (int mt = 0; mt < 2; mt++)
                #pragma unroll
                for (int nt = 0; nt < 8; nt++)
                    mma16816(acc[mt][nt], a[mt], &bq[nt >> 1][(nt & 1) * 2]);
        }
    }
    __syncthreads();   // all warps done reading A/B before epilogue overwrites

    if (do_wait) {
        if (tid == 0) {
            volatile int* vf = (volatile int*)flags;
            while (vf[17 + cloud] < 32) __nanosleep(100);
            while (vf[1 + cloud] < 16) __nanosleep(100);
        }
        __syncthreads();
        __threadfence();
    }

    // epilogue: bias + y-gather + relu -> smem H1 chunks (stage layout)
    #pragma unroll
    for (int mt = 0; mt < 2; mt++)
        #pragma unroll
        for (int half = 0; half < 2; half++) {
            const int r2 = wm * 32 + mt * 16 + g + half * 8;
            const int r = row0 + r2;
            const int i0 = gidx[r * 3 + 0], i1 = gidx[r * 3 + 1], i2 = gidx[r * 3 + 2];
            const float w0 = gw[r * 3 + 0], w1 = gw[r * 3 + 1], w2 = gw[r * 3 + 2];
            #pragma unroll
            for (int nt = 0; nt < 8; nt++) {
                const int ccol = wn * 64 + nt * 8 + 2 * t;
                const int gcol = bx * 128 + ccol;
                float vx = acc[mt][nt][half * 2 + 0];
                float vy = acc[mt][nt][half * 2 + 1];
                float2 bb = *(const float2*)&b1[gcol];
                float2 y0 = __half22float2(*(const __half2*)&yh[(size_t)i0 * C_HID + gcol]);
                float2 y1 = __half22float2(*(const __half2*)&yh[(size_t)i1 * C_HID + gcol]);
                float2 y2 = __half22float2(*(const __half2*)&yh[(size_t)i2 * C_HID + gcol]);
                vx = fmaxf(vx + bb.x + w0 * y0.x + w1 * y1.x + w2 * y2.x, 0.f);
                vy = fmaxf(vy + bb.y + w0 * y0.y + w1 * y1.y + w2 * y2.y, 0.f);
                __half2 h2 = __halves2half2(__float2half_rn(vx), __float2half_rn(vy));
                const uint32_t off = (uint32_t)((bx * 4 + (ccol >> 5)) * CH_BYTES
                                                + r2 * 80 + (ccol & 31) * 2);
                *(__half2*)(smem + off) = h2;
            }
        }
    __syncthreads();
}

// ---------------- G3 phase: out col-tile from smem h1 (3-stage B, 8 chunks) -
__device__ __forceinline__ void g3_phase(
    char* smem, uint32_t sb,
    const __half* __restrict__ w2t, const float* __restrict__ b2,
    float* __restrict__ outp, int row0, int bxx)
{
    const int tid = threadIdx.x;
    const int wid = tid >> 5, lane = tid & 31;
    const int g = lane >> 2, t = lane & 3;
    const int wm = wid & 3, wn = wid >> 2;

    const int lrow = tid >> 1;
    const int lch  = (tid & 1) * 2;
    const uint32_t stB = sb + SMEM_G3B + (uint32_t)(lrow * 80 + lch * 16);
    const __half* gB = w2t + (size_t)(bxx * 128 + lrow) * C_HID + lch * 8;

    uint32_t aAddr[2], bAddr[4];
    #pragma unroll
    for (int mt = 0; mt < 2; mt++)
        aAddr[mt] = sb + (uint32_t)(((wm * 32 + mt * 16 + (lane & 15)) * PITCH
                                     + (lane >> 4) * 8) * 2);
    #pragma unroll
    for (int p = 0; p < 4; p++)
        bAddr[p] = sb + SMEM_G3B + (uint32_t)(((wn * 64 + p * 16 + (lane & 7)
                                     + ((lane >> 4) & 1) * 8) * PITCH
                                     + ((lane >> 3) & 1) * 8) * 2);

    float acc[2][8][4];
    #pragma unroll
    for (int mt = 0; mt < 2; mt++)
        #pragma unroll
        for (int nt = 0; nt < 8; nt++)
            #pragma unroll
            for (int e = 0; e < 4; e++) acc[mt][nt][e] = 0.f;

    __syncthreads();   // h1 writes / prior B-stage readers complete

    #pragma unroll
    for (int s = 0; s < 2; s++) {
        const uint32_t o = s * CH_BYTES;
        cp16(stB + o, gB + s * 32); cp16(stB + o + 16, gB + s * 32 + 8);
        CP_COMMIT();
    }

    #pragma unroll
    for (int c = 0; c < 8; c++) {
        if (c + 1 < 8) { CP_WAIT(1); } else { CP_WAIT(0); }
        __syncthreads();
        if (c + 2 < 8) {
            const int c2 = c + 2;
            const uint32_t o = (c2 % 3) * CH_BYTES;
            cp16(stB + o, gB + c2 * 32); cp16(stB + o + 16, gB + c2 * 32 + 8);
            CP_COMMIT();
        }
        #pragma unroll
        for (int ks = 0; ks < 2; ks++) {
            const uint32_t koA = c * CH_BYTES + ks * 32;
            const uint32_t koB = (c % 3) * CH_BYTES + ks * 32;
            uint32_t a[2][4], bq[4][4];
            LDSM4(a[0], aAddr[0] + koA);
            LDSM4(a[1], aAddr[1] + koA);
            LDSM4(bq[0], bAddr[0] + koB);
            LDSM4(bq[1], bAddr[1] + koB);
            LDSM4(bq[2], bAddr[2] + koB);
            LDSM4(bq[3], bAddr[3] + koB);
            #pragma unroll
            for (int mt = 0; mt < 2; mt++)
                #pragma unroll
                for (int nt = 0; nt < 8; nt++)
                    mma16816(acc[mt][nt], a[mt], &bq[nt >> 1][(nt & 1) * 2]);
        }
    }

    // epilogue: bias + relu -> fp32 out
    #pragma unroll
    for (int mt = 0; mt < 2; mt++)
        #pragma unroll
        for (int half = 0; half < 2; half++) {
            const int r = row0 + wm * 32 + mt * 16 + g + half * 8;
            #pragma unroll
            for (int nt = 0; nt < 8; nt++) {
                const int ccol = wn * 64 + nt * 8 + 2 * t;
                const int gcol = bxx * 128 + ccol;
                float2 bb = *(const float2*)&b2[gcol];
                float vx = fmaxf(acc[mt][nt][half * 2 + 0] + bb.x, 0.f);
                float vy = fmaxf(acc[mt][nt][half * 2 + 1] + bb.y, 0.f);
                *(float2*)&outp[(size_t)r * C_HID + gcol] = make_float2(vx, vy);
            }
        }
}

// ---------------- mega kernel: G1 (256) + fused G2+G3 (512) -----------------
#define G1_TILES 256
#define FUSED_TILES 512

__global__ __launch_bounds__(256, 2) void mega_gemm(
    const __half* __restrict__ xh, const __half* __restrict__ xsh,
    const __half* __restrict__ w1a, const __half* __restrict__ w1b,
    const __half* __restrict__ w2t,
    const float* __restrict__ b1, const float* __restrict__ b2,
    __half* __restrict__ yh, float* __restrict__ outp,
    const int* __restrict__ gidx, const float* __restrict__ gw,
    int* __restrict__ flags)
{
    extern __shared__ __align__(16) char smem[];
    const uint32_t sb = smem_u32(smem);
    const int t = blockIdx.x;
    const int tid = threadIdx.x;

    if (t < G1_TILES) {
        const int bx = t & 1, by = t >> 1;
        gemm_g1(xh, w1a, yh, by * 128, bx * 128, smem, sb);
        __threadfence();
        __syncthreads();
        if (tid == 0) atomicAdd(&flags[1 + (by >> 3)], 1);
    } else {
        const int u = t - G1_TILES;           // row block 0..511
        const int row0 = u * 128;
        const int cloud = u >> 5;
        g2_phase(smem, sb, true,  xsh, w1b, b1, yh, gidx, gw, flags, cloud, true,  row0, 0);
        g2_phase(smem, sb, false, xsh, w1b, b1, yh, gidx, gw, flags, cloud, false, row0, 1);
        g3_phase(smem, sb, w2t, b2, outp, row0, 0);
        g3_phase(smem, sb, w2t, b2, outp, row0, 1);
    }
}

// batch_skip int32 -> float (tuple tail)
__global__ void cast_batch_kernel(const int* __restrict__ b, float* __restrict__ out, int n)
{
    int i = blockIdx.x * blockDim.x + threadIdx.x;
    if (i < n) out[i] = (float)b[i];
}

// ---------------------------------------------------------------------------
extern "C" void kernel_launch(void* const* d_in, const int* in_sizes, int n_in,
                              void* d_out, int out_size)
{
    (void)in_sizes; (void)n_in;
    const float* x        = (const float*)d_in[0];
    const float* pos      = (const float*)d_in[1];
    const float* x_skip   = (const float*)d_in[2];
    const float* pos_skip = (const float*)d_in[3];
    const float* W1       = (const float*)d_in[4];
    const float* b1       = (const float*)d_in[5];
    const float* W2       = (const float*)d_in[6];
    const float* b2       = (const float*)d_in[7];

    float* w; int *idx, *flags;
    __half *yh, *xh, *xsh, *w1a, *w1b, *w2t;
    cudaGetSymbolAddress((void**)&yh,    g_yh);
    cudaGetSymbolAddress((void**)&idx,   g_idx);
    cudaGetSymbolAddress((void**)&w,     g_w);
    cudaGetSymbolAddress((void**)&xh,    g_xh);
    cudaGetSymbolAddress((void**)&xsh,   g_xsh);
    cudaGetSymbolAddress((void**)&w1a,   g_w1a);
    cudaGetSymbolAddress((void**)&w1b,   g_w1b);
    cudaGetSymbolAddress((void**)&w2t,   g_w2t);
    cudaGetSymbolAddress((void**)&flags, g_flags);

    static bool init_done = false;
    static cudaStream_t s_knn, s_aux;
    static cudaEvent_t ev_fork, ev_knn, ev_aux, ev_tail;
    if (!init_done) {
        cudaFuncSetAttribute(mega_gemm, cudaFuncAttributeMaxDynamicSharedMemorySize, SM_BYTES);
        int prio_lo = 0, prio_hi = 0;
        cudaDeviceGetStreamPriorityRange(&prio_lo, &prio_hi);
        cudaStreamCreateWithPriority(&s_knn, cudaStreamNonBlocking, prio_hi);
        cudaStreamCreateWithFlags(&s_aux, cudaStreamNonBlocking);
        cudaEventCreateWithFlags(&ev_fork, cudaEventDisableTiming);
        cudaEventCreateWithFlags(&ev_knn, cudaEventDisableTiming);
        cudaEventCreateWithFlags(&ev_aux, cudaEventDisableTiming);
        cudaEventCreateWithFlags(&ev_tail, cudaEventDisableTiming);
        init_done = true;
    }

    const long long H_ELEMS   = (long long)NF_TOT * C_HID;
    const long long POS_ELEMS = (long long)NF_TOT * 3;

    // reset flags BEFORE forking knn (knn increments flags[17..32])
    cudaMemsetAsync(flags, 0, 64 * sizeof(int), 0);
    cudaEventRecord(ev_fork, 0);

    // side stream 1 (high priority): kNN, per-cloud self-signaling
    cudaStreamWaitEvent(s_knn, ev_fork, 0);
    knn_kernel<<<BATCH * (N_FINE / 128), 128, 0, s_knn>>>(pos, pos_skip, idx, w, flags);
    cudaEventRecord(ev_knn, s_knn);

    // side stream 2: weight cast + xsh cast (mega deps), then tuple-tail ops
    cudaStreamWaitEvent(s_aux, ev_fork, 0);
    cast_w_tiled<<<160, 256, 0, s_aux>>>(W1, W2, w1a, w1b, w2t);
    cast_act<<<(NF_TOT * C_SKIP / 4 + 255) / 256, 256, 0, s_aux>>>(
        x_skip, xsh, NF_TOT * C_SKIP / 4);
    cudaEventRecord(ev_aux, s_aux);
    // tuple tail (independent of mega; overlaps it)
    if ((long long)out_size >= H_ELEMS + POS_ELEMS) {
        cudaMemcpyAsync((float*)d_out + H_ELEMS, pos_skip,
                        POS_ELEMS * sizeof(float), cudaMemcpyDeviceToDevice, s_aux);
    }
    if ((long long)out_size >= H_ELEMS + POS_ELEMS + NF_TOT) {
        const int* batch_skip = (const int*)d_in[9];
        cast_batch_kernel<<<(NF_TOT + 255) / 256, 256, 0, s_aux>>>(
            batch_skip, (float*)d_out + H_ELEMS + POS_ELEMS, NF_TOT);
    }

    // main stream: xh cast only, then mega
    cast_act<<<(NC_TOT * C_IN / 4 + 255) / 256, 256>>>(x, xh, NC_TOT * C_IN / 4);

    cudaStreamWaitEvent(0, ev_aux, 0);
    mega_gemm<<<G1_TILES + FUSED_TILES, 256, SM_BYTES>>>(
        xh, xsh, w1a, w1b, w2t, b1, b2,
        yh, (float*)d_out, idx, w, flags);

    // join side streams for graph completeness
    cudaStreamWaitEvent(0, ev_knn, 0);
    cudaEventRecord(ev_tail, s_aux);
    cudaStreamWaitEvent(0, ev_tail, 0);
}